// round 1
// baseline (speedup 1.0000x reference)
#include <cuda_runtime.h>
#include <cstdint>

// ---------------------------------------------------------------------------
// Problem constants
// ---------------------------------------------------------------------------
#define BB     128          // batch
#define DD     256          // embedding dim
#define NSAMP  1000         // MC samples
#define KK     8            // top-k
#define NSHAPES 8000
#define HALF_ELEMS 8192000u // (128*1000*128)/2  -> row b pairs with row b+64

#define NEG_INF __int_as_float(0xff800000)

// ---------------------------------------------------------------------------
// Device scratch (no allocations allowed)
// ---------------------------------------------------------------------------
__device__ float  g_pred[BB * BB];
__device__ float  g_tgt [BB * BB];
__device__ int    g_cnt1[BB * KK * BB];   // pred-side indicator counts
__device__ int    g_cnt2[BB * KK * BB];   // tgt-side indicator counts
__device__ double g_partial[BB];

// ---------------------------------------------------------------------------
// threefry2x32 — exactly JAX's schedule
// ---------------------------------------------------------------------------
__host__ __device__ __forceinline__ void threefry2x32(
    uint32_t k0, uint32_t k1, uint32_t x0, uint32_t x1,
    uint32_t& o0, uint32_t& o1)
{
    uint32_t ks2 = k0 ^ k1 ^ 0x1BD11BDAu;
#define TF_ROUND(r) { x0 += x1; x1 = (x1 << (r)) | (x1 >> (32 - (r))); x1 ^= x0; }
    x0 += k0; x1 += k1;
    TF_ROUND(13) TF_ROUND(15) TF_ROUND(26) TF_ROUND(6)
    x0 += k1;  x1 += ks2 + 1u;
    TF_ROUND(17) TF_ROUND(29) TF_ROUND(16) TF_ROUND(24)
    x0 += ks2; x1 += k0 + 2u;
    TF_ROUND(13) TF_ROUND(15) TF_ROUND(26) TF_ROUND(6)
    x0 += k0;  x1 += k1 + 3u;
    TF_ROUND(17) TF_ROUND(29) TF_ROUND(16) TF_ROUND(24)
    x0 += k1;  x1 += ks2 + 4u;
    TF_ROUND(13) TF_ROUND(15) TF_ROUND(26) TF_ROUND(6)
    x0 += ks2; x1 += k0 + 5u;
#undef TF_ROUND
    o0 = x0; o1 = x1;
}

// ---------------------------------------------------------------------------
// bits -> N(0,1) exactly like jax.random.normal (uniform bit-trick + XLA ErfInv32)
// ---------------------------------------------------------------------------
__device__ __forceinline__ float jx_normal(uint32_t bits)
{
    float f = __uint_as_float((bits >> 9) | 0x3f800000u) - 1.0f;   // [0,1)
    const float lo = -0.99999994f;                                  // nextafter(-1,0)
    float u = __fadd_rn(__fmul_rn(f, 2.0f), lo);                    // maxval-minval == 2.0f
    u = fmaxf(u, lo);

    float w = -log1pf(-__fmul_rn(u, u));
    float p;
    if (w < 5.0f) {
        w -= 2.5f;
        p = 2.81022636e-08f;
        p = fmaf(p, w,  3.43273939e-07f);
        p = fmaf(p, w, -3.5233877e-06f);
        p = fmaf(p, w, -4.39150654e-06f);
        p = fmaf(p, w,  0.00021858087f);
        p = fmaf(p, w, -0.00125372503f);
        p = fmaf(p, w, -0.00417768164f);
        p = fmaf(p, w,  0.246640727f);
        p = fmaf(p, w,  1.50140941f);
    } else {
        w = sqrtf(w) - 3.0f;
        p = -0.000200214257f;
        p = fmaf(p, w,  0.000100950558f);
        p = fmaf(p, w,  0.00134934322f);
        p = fmaf(p, w, -0.00367342844f);
        p = fmaf(p, w,  0.00573950773f);
        p = fmaf(p, w, -0.0076224613f);
        p = fmaf(p, w,  0.00943887047f);
        p = fmaf(p, w,  1.00167406f);
        p = fmaf(p, w,  2.83297682f);
    }
    return __fmul_rn(1.41421354f, __fmul_rn(p, u));   // sqrt(2)*erfinv(u)
}

__device__ __forceinline__ float perturb(float x, uint32_t bits, float sigma)
{
    // matches ref: x + sigma*noise as separate mul + add (no fma contraction)
    return __fadd_rn(x, __fmul_rn(sigma, jx_normal(bits)));
}

// ---------------------------------------------------------------------------
// Warp-cooperative top-8 of 128 values (4 per lane, idx = lane + 32*q),
// sorted ascending by index, counted into shared counters.
// Tie-break: lowest index first (matches stable XLA top_k).
// ---------------------------------------------------------------------------
__device__ __forceinline__ void topk8_accum(float v0, float v1, float v2, float v3,
                                            int lane, int* __restrict__ scnt)
{
    int wi[8];
#pragma unroll
    for (int r = 0; r < 8; ++r) {
        float mv = v0; int mi = lane;
        if (v1 > mv) { mv = v1; mi = lane + 32; }
        if (v2 > mv) { mv = v2; mi = lane + 64; }
        if (v3 > mv) { mv = v3; mi = lane + 96; }
#pragma unroll
        for (int off = 16; off > 0; off >>= 1) {
            float ov = __shfl_xor_sync(0xffffffffu, mv, off);
            int   oi = __shfl_xor_sync(0xffffffffu, mi, off);
            if (ov > mv || (ov == mv && oi < mi)) { mv = ov; mi = oi; }
        }
        wi[r] = mi;
        if ((mi & 31) == lane) {
            int q = mi >> 5;
            if      (q == 0) v0 = NEG_INF;
            else if (q == 1) v1 = NEG_INF;
            else if (q == 2) v2 = NEG_INF;
            else             v3 = NEG_INF;
        }
    }
    // Batcher odd-even mergesort, 19 comparators, ascending
#define CE(i, j) { int _a = wi[i], _b = wi[j]; wi[i] = min(_a,_b); wi[j] = max(_a,_b); }
    CE(0,1) CE(2,3) CE(4,5) CE(6,7)
    CE(0,2) CE(1,3) CE(4,6) CE(5,7)
    CE(1,2) CE(5,6)
    CE(0,4) CE(1,5) CE(2,6) CE(3,7)
    CE(2,4) CE(3,5)
    CE(1,2) CE(3,4) CE(5,6)
#undef CE
    if (lane < 8) {
        int idx = wi[0];
        idx = (lane == 1) ? wi[1] : idx;
        idx = (lane == 2) ? wi[2] : idx;
        idx = (lane == 3) ? wi[3] : idx;
        idx = (lane == 4) ? wi[4] : idx;
        idx = (lane == 5) ? wi[5] : idx;
        idx = (lane == 6) ? wi[6] : idx;
        idx = (lane == 7) ? wi[7] : idx;
        atomicAdd(&scnt[lane * 128 + idx], 1);
    }
}

// ---------------------------------------------------------------------------
// Kernel 0: zero count arrays
// ---------------------------------------------------------------------------
__global__ void zero_counts_kernel()
{
    int i = blockIdx.x * blockDim.x + threadIdx.x;
    if (i < BB * KK * BB) { g_cnt1[i] = 0; g_cnt2[i] = 0; }
}

// ---------------------------------------------------------------------------
// Kernel 1: pred_sim = scan @ cad^T ; tgt_sim gather
// grid(128) x block(128): block = output row i, thread = column j
// ---------------------------------------------------------------------------
__global__ void __launch_bounds__(128) prep_kernel(
    const float* __restrict__ cad, const float* __restrict__ scan,
    const float* __restrict__ sim, const int* __restrict__ scannet_idx,
    const int* __restrict__ shapenet_idx)
{
    __shared__ float row[DD];
    int i = blockIdx.x, j = threadIdx.x;
    row[j]       = scan[i * DD + j];
    row[j + 128] = scan[i * DD + 128 + j];
    __syncthreads();

    const float4* c4 = reinterpret_cast<const float4*>(cad + (size_t)j * DD);
    float acc = 0.0f;
#pragma unroll 8
    for (int t = 0; t < DD / 4; ++t) {
        float4 v = c4[t];
        acc = fmaf(row[4 * t + 0], v.x, acc);
        acc = fmaf(row[4 * t + 1], v.y, acc);
        acc = fmaf(row[4 * t + 2], v.z, acc);
        acc = fmaf(row[4 * t + 3], v.w, acc);
    }
    g_pred[i * BB + j] = acc;
    g_tgt[i * BB + j]  = sim[(size_t)scannet_idx[i] * NSHAPES + shapenet_idx[j]];
}

// ---------------------------------------------------------------------------
// Kernel 2: noise generation + perturbed top-8 counting.
// grid(64, NCHUNK), block(256)=8 warps. blockIdx.x = bLow in [0,64);
// one warp-sample produces noise for rows bLow AND bLow+64 (threefry pair).
// ---------------------------------------------------------------------------
__global__ void __launch_bounds__(256) noise_topk_kernel(
    int which, uint32_t k0, uint32_t k1, float sigma, int nPerChunk)
{
    __shared__ float sLow[BB], sHigh[BB];
    __shared__ int   sCnt[2 * KK * BB];     // [half][k][d]

    const float* __restrict__ src = which ? g_tgt  : g_pred;
    int*         __restrict__ cnt = which ? g_cnt2 : g_cnt1;

    int tid  = threadIdx.x;
    int bLow = blockIdx.x;

    if (tid < BB) {
        sLow[tid]  = src[bLow * BB + tid];
        sHigh[tid] = src[(bLow + 64) * BB + tid];
    }
    for (int i = tid; i < 2 * KK * BB; i += 256) sCnt[i] = 0;
    __syncthreads();

    int warp = tid >> 5, lane = tid & 31;
    float xL0 = sLow[lane], xL1 = sLow[lane + 32], xL2 = sLow[lane + 64], xL3 = sLow[lane + 96];
    float xH0 = sHigh[lane], xH1 = sHigh[lane + 32], xH2 = sHigh[lane + 64], xH3 = sHigh[lane + 96];

    int nBegin = blockIdx.y * nPerChunk;
    int nEnd   = nBegin + nPerChunk;

    for (int n = nBegin + warp; n < nEnd; n += 8) {
        uint32_t c = (uint32_t)(bLow * (NSAMP * BB) + n * BB) + (uint32_t)lane;
        uint32_t r0, r1;
        float a0, a1, a2, a3, h0, h1, h2, h3;

        threefry2x32(k0, k1, c,        c + HALF_ELEMS,        r0, r1);
        a0 = perturb(xL0, r0, sigma);  h0 = perturb(xH0, r1, sigma);
        threefry2x32(k0, k1, c + 32u,  c + HALF_ELEMS + 32u,  r0, r1);
        a1 = perturb(xL1, r0, sigma);  h1 = perturb(xH1, r1, sigma);
        threefry2x32(k0, k1, c + 64u,  c + HALF_ELEMS + 64u,  r0, r1);
        a2 = perturb(xL2, r0, sigma);  h2 = perturb(xH2, r1, sigma);
        threefry2x32(k0, k1, c + 96u,  c + HALF_ELEMS + 96u,  r0, r1);
        a3 = perturb(xL3, r0, sigma);  h3 = perturb(xH3, r1, sigma);

        topk8_accum(a0, a1, a2, a3, lane, sCnt);
        topk8_accum(h0, h1, h2, h3, lane, sCnt + KK * BB);
    }
    __syncthreads();

    for (int i = tid; i < 2 * KK * BB; i += 256) {
        int half = i >> 10;              // 0 -> row bLow, 1 -> row bLow+64
        int rem  = i & 1023;             // k*128 + d
        int row  = bLow + (half << 6);
        int v = sCnt[i];
        if (v) atomicAdd(&cnt[row * (KK * BB) + rem], v);
    }
}

// ---------------------------------------------------------------------------
// Kernel 3/4: deterministic reduction
// loss = -sum(c1*c2*tgt) / (1000*1000*1024)
// ---------------------------------------------------------------------------
__global__ void __launch_bounds__(256) reduce1_kernel()
{
    __shared__ double sd[256];
    int b = blockIdx.x;
    double acc = 0.0;
    for (int i = threadIdx.x; i < KK * BB; i += 256) {
        int d = i & 127;
        acc += (double)g_cnt1[b * (KK * BB) + i] *
               (double)g_cnt2[b * (KK * BB) + i] *
               (double)g_tgt[b * BB + d];
    }
    sd[threadIdx.x] = acc;
    __syncthreads();
    for (int s = 128; s > 0; s >>= 1) {
        if (threadIdx.x < s) sd[threadIdx.x] += sd[threadIdx.x + s];
        __syncthreads();
    }
    if (threadIdx.x == 0) g_partial[b] = sd[0];
}

__global__ void __launch_bounds__(128) reduce2_kernel(float* __restrict__ out)
{
    __shared__ double sd[128];
    sd[threadIdx.x] = g_partial[threadIdx.x];
    __syncthreads();
    for (int s = 64; s > 0; s >>= 1) {
        if (threadIdx.x < s) sd[threadIdx.x] += sd[threadIdx.x + s];
        __syncthreads();
    }
    if (threadIdx.x == 0)
        out[0] = (float)(-sd[0] / (1000.0 * 1000.0 * (double)(KK * BB)));
}

// ---------------------------------------------------------------------------
// Launch
// ---------------------------------------------------------------------------
extern "C" void kernel_launch(void* const* d_in, const int* in_sizes, int n_in,
                              void* d_out, int out_size)
{
    (void)in_sizes; (void)n_in; (void)out_size;
    const float* cad   = (const float*)d_in[0];
    const float* scan  = (const float*)d_in[1];
    const float* sim   = (const float*)d_in[2];
    const int*   sidx  = (const int*)d_in[3];
    const int*   shidx = (const int*)d_in[4];
    float*       out   = (float*)d_out;

    // nk1, nk2 = jax.random.split(jax.random.key(42)); key(42) = (0, 42)
    // split -> threefry2x32(key, iota(4)): pairs (0,2),(1,3);
    // result rows: nk1=(o0_p0, o0_p1), nk2=(o1_p0, o1_p1)
    uint32_t o00, o10, o01, o11;
    threefry2x32(0u, 42u, 0u, 2u, o00, o10);
    threefry2x32(0u, 42u, 1u, 3u, o01, o11);
    uint32_t nk1_0 = o00, nk1_1 = o01;
    uint32_t nk2_0 = o10, nk2_1 = o11;

    const float sig1 = 0.05f;
    const float sig2 = (float)(0.05 / 200.0);

    zero_counts_kernel<<<(BB * KK * BB + 255) / 256, 256>>>();
    prep_kernel<<<BB, 128>>>(cad, scan, sim, sidx, shidx);

    const int NCHUNK = 10;                 // 100 samples per chunk
    dim3 grid(64, NCHUNK);
    noise_topk_kernel<<<grid, 256>>>(0, nk1_0, nk1_1, sig1, NSAMP / NCHUNK);
    noise_topk_kernel<<<grid, 256>>>(1, nk2_0, nk2_1, sig2, NSAMP / NCHUNK);

    reduce1_kernel<<<BB, 256>>>();
    reduce2_kernel<<<1, 128>>>(out);
}

// round 2
// speedup vs baseline: 1.8677x; 1.8677x over previous
#include <cuda_runtime.h>
#include <cstdint>

// ---------------------------------------------------------------------------
// Problem constants
// ---------------------------------------------------------------------------
#define BB     128          // batch
#define DD     256          // embedding dim
#define NSAMP  1000         // MC samples
#define KK     8            // top-k
#define NSHAPES 8000
#define HALF_ELEMS 8192000u // (128*1000*128)/2 -> row b pairs with row b+64

// ---------------------------------------------------------------------------
// Device scratch (no allocations allowed)
// ---------------------------------------------------------------------------
__device__ float  g_pred[BB * BB];
__device__ float  g_tgt [BB * BB];
__device__ int    g_cnt1[BB * KK * BB];   // pred-side indicator counts
__device__ int    g_cnt2[BB * KK * BB];   // tgt-side indicator counts
__device__ double g_partial[BB];

// ---------------------------------------------------------------------------
// threefry2x32 — exactly JAX's schedule
// ---------------------------------------------------------------------------
__host__ __device__ __forceinline__ void threefry2x32(
    uint32_t k0, uint32_t k1, uint32_t x0, uint32_t x1,
    uint32_t& o0, uint32_t& o1)
{
    uint32_t ks2 = k0 ^ k1 ^ 0x1BD11BDAu;
#define TF_ROUND(r) { x0 += x1; x1 = (x1 << (r)) | (x1 >> (32 - (r))); x1 ^= x0; }
    x0 += k0; x1 += k1;
    TF_ROUND(13) TF_ROUND(15) TF_ROUND(26) TF_ROUND(6)
    x0 += k1;  x1 += ks2 + 1u;
    TF_ROUND(17) TF_ROUND(29) TF_ROUND(16) TF_ROUND(24)
    x0 += ks2; x1 += k0 + 2u;
    TF_ROUND(13) TF_ROUND(15) TF_ROUND(26) TF_ROUND(6)
    x0 += k0;  x1 += k1 + 3u;
    TF_ROUND(17) TF_ROUND(29) TF_ROUND(16) TF_ROUND(24)
    x0 += k1;  x1 += ks2 + 4u;
    TF_ROUND(13) TF_ROUND(15) TF_ROUND(26) TF_ROUND(6)
    x0 += ks2; x1 += k0 + 5u;
#undef TF_ROUND
    o0 = x0; o1 = x1;
}

// ---------------------------------------------------------------------------
// bits -> N(0,1) exactly like jax.random.normal (uniform bit-trick + XLA ErfInv32)
// ---------------------------------------------------------------------------
__device__ __forceinline__ float jx_normal(uint32_t bits)
{
    float f = __uint_as_float((bits >> 9) | 0x3f800000u) - 1.0f;   // [0,1)
    const float lo = -0.99999994f;                                  // nextafter(-1,0)
    float u = __fadd_rn(__fmul_rn(f, 2.0f), lo);
    u = fmaxf(u, lo);

    float w = -log1pf(-__fmul_rn(u, u));
    float p;
    if (w < 5.0f) {
        w -= 2.5f;
        p = 2.81022636e-08f;
        p = fmaf(p, w,  3.43273939e-07f);
        p = fmaf(p, w, -3.5233877e-06f);
        p = fmaf(p, w, -4.39150654e-06f);
        p = fmaf(p, w,  0.00021858087f);
        p = fmaf(p, w, -0.00125372503f);
        p = fmaf(p, w, -0.00417768164f);
        p = fmaf(p, w,  0.246640727f);
        p = fmaf(p, w,  1.50140941f);
    } else {
        w = sqrtf(w) - 3.0f;
        p = -0.000200214257f;
        p = fmaf(p, w,  0.000100950558f);
        p = fmaf(p, w,  0.00134934322f);
        p = fmaf(p, w, -0.00367342844f);
        p = fmaf(p, w,  0.00573950773f);
        p = fmaf(p, w, -0.0076224613f);
        p = fmaf(p, w,  0.00943887047f);
        p = fmaf(p, w,  1.00167406f);
        p = fmaf(p, w,  2.83297682f);
    }
    return __fmul_rn(1.41421354f, __fmul_rn(p, u));   // sqrt(2)*erfinv(u)
}

// perturbed value -> monotonic uint key (exact order-isomorphic float mapping)
__device__ __forceinline__ uint32_t perturb_key(float x, uint32_t bits, float sigma)
{
    float v = __fadd_rn(x, __fmul_rn(sigma, jx_normal(bits)));
    uint32_t b = __float_as_uint(v);
    return b ^ ((uint32_t)((int32_t)b >> 31) | 0x80000000u);
}

// ---------------------------------------------------------------------------
// Tournament top-8 over 128 keys (4/lane), both halves interleaved for ILP.
// Tie-break: lowest index (== XLA stable top_k). Output: counts by
// (rank-after-index-sort, index) into shared counters.
// ---------------------------------------------------------------------------
#define CED(ux,uy,ix,iy) { bool s_ = (ux) < (uy); uint32_t tu_ = s_?(uy):(ux); \
    (uy) = s_?(ux):(uy); (ux) = tu_; int ti_ = s_?(iy):(ix); (iy) = s_?(ix):(iy); (ix) = ti_; }
#define CEA(x,y) { int a_ = min(x,y); (y) = max(x,y); (x) = a_; }

__device__ __forceinline__ void topk8_pair_accum(
    uint32_t a0, uint32_t a1, uint32_t a2, uint32_t a3,
    uint32_t b0, uint32_t b1, uint32_t b2, uint32_t b3,
    int lane, int* __restrict__ scnt)
{
    int ga0 = lane, ga1 = lane + 32, ga2 = lane + 64, ga3 = lane + 96;
    int gb0 = lane, gb1 = lane + 32, gb2 = lane + 64, gb3 = lane + 96;

    // per-lane descending sort of 4 (key, idx) pairs
    CED(a0,a1,ga0,ga1) CED(a2,a3,ga2,ga3) CED(a0,a2,ga0,ga2) CED(a1,a3,ga1,ga3) CED(a1,a2,ga1,ga2)
    CED(b0,b1,gb0,gb1) CED(b2,b3,gb2,gb3) CED(b0,b2,gb0,gb2) CED(b1,b3,gb1,gb3) CED(b1,b2,gb1,gb2)

    uint32_t huA = a0, huB = b0;
    int hgA = ga0, hgB = gb0;
    int posA = 0, posB = 0;
    int wA[8], wB[8];

#pragma unroll
    for (int r = 0; r < 8; ++r) {
        uint32_t mA = __reduce_max_sync(0xffffffffu, huA);
        uint32_t mB = __reduce_max_sync(0xffffffffu, huB);
        int wiA = __reduce_min_sync(0xffffffffu, (huA == mA) ? hgA : 128);
        int wiB = __reduce_min_sync(0xffffffffu, (huB == mB) ? hgB : 128);
        wA[r] = wiA; wB[r] = wiB;
        bool wonA = (hgA == wiA);
        bool wonB = (hgB == wiB);
        posA += wonA; posB += wonB;
        uint32_t cuA = (posA == 1) ? a1 : (posA == 2) ? a2 : (posA == 3) ? a3 : 0u;
        int      cgA = (posA == 1) ? ga1 : (posA == 2) ? ga2 : (posA == 3) ? ga3 : 255;
        uint32_t cuB = (posB == 1) ? b1 : (posB == 2) ? b2 : (posB == 3) ? b3 : 0u;
        int      cgB = (posB == 1) ? gb1 : (posB == 2) ? gb2 : (posB == 3) ? gb3 : 255;
        huA = wonA ? cuA : huA;  hgA = wonA ? cgA : hgA;
        huB = wonB ? cuB : huB;  hgB = wonB ? cgB : hgB;
    }

    // sort 8 winner indices ascending (Batcher, 19 comparators; uniform data)
#define SORT8(w) \
    CEA(w[0],w[1]) CEA(w[2],w[3]) CEA(w[4],w[5]) CEA(w[6],w[7]) \
    CEA(w[0],w[2]) CEA(w[1],w[3]) CEA(w[4],w[6]) CEA(w[5],w[7]) \
    CEA(w[1],w[2]) CEA(w[5],w[6]) \
    CEA(w[0],w[4]) CEA(w[1],w[5]) CEA(w[2],w[6]) CEA(w[3],w[7]) \
    CEA(w[2],w[4]) CEA(w[3],w[5]) \
    CEA(w[1],w[2]) CEA(w[3],w[4]) CEA(w[5],w[6])
    SORT8(wA)
    SORT8(wB)
#undef SORT8

    // lanes 0-7 count half A, lanes 8-15 count half B, one ATOMS total
    int r = lane & 7;
    int ia = wA[0];
    ia = (r == 1) ? wA[1] : ia; ia = (r == 2) ? wA[2] : ia; ia = (r == 3) ? wA[3] : ia;
    ia = (r == 4) ? wA[4] : ia; ia = (r == 5) ? wA[5] : ia; ia = (r == 6) ? wA[6] : ia;
    ia = (r == 7) ? wA[7] : ia;
    int ib = wB[0];
    ib = (r == 1) ? wB[1] : ib; ib = (r == 2) ? wB[2] : ib; ib = (r == 3) ? wB[3] : ib;
    ib = (r == 4) ? wB[4] : ib; ib = (r == 5) ? wB[5] : ib; ib = (r == 6) ? wB[6] : ib;
    ib = (r == 7) ? wB[7] : ib;
    int idx = (lane < 8) ? ia : ib;
    if (lane < 16)
        atomicAdd(&scnt[((lane >> 3) * (KK * BB)) + r * BB + idx], 1);
}

// ---------------------------------------------------------------------------
// Kernel 0: zero count arrays
// ---------------------------------------------------------------------------
__global__ void zero_counts_kernel()
{
    int i = blockIdx.x * blockDim.x + threadIdx.x;
    if (i < BB * KK * BB) { g_cnt1[i] = 0; g_cnt2[i] = 0; }
}

// ---------------------------------------------------------------------------
// Kernel 1: pred_sim = scan @ cad^T ; tgt_sim gather
// ---------------------------------------------------------------------------
__global__ void __launch_bounds__(128) prep_kernel(
    const float* __restrict__ cad, const float* __restrict__ scan,
    const float* __restrict__ sim, const int* __restrict__ scannet_idx,
    const int* __restrict__ shapenet_idx)
{
    __shared__ float row[DD];
    int i = blockIdx.x, j = threadIdx.x;
    row[j]       = scan[i * DD + j];
    row[j + 128] = scan[i * DD + 128 + j];
    __syncthreads();

    const float4* c4 = reinterpret_cast<const float4*>(cad + (size_t)j * DD);
    float acc = 0.0f;
#pragma unroll 8
    for (int t = 0; t < DD / 4; ++t) {
        float4 v = c4[t];
        acc = fmaf(row[4 * t + 0], v.x, acc);
        acc = fmaf(row[4 * t + 1], v.y, acc);
        acc = fmaf(row[4 * t + 2], v.z, acc);
        acc = fmaf(row[4 * t + 3], v.w, acc);
    }
    g_pred[i * BB + j] = acc;
    g_tgt[i * BB + j]  = sim[(size_t)scannet_idx[i] * NSHAPES + shapenet_idx[j]];
}

// ---------------------------------------------------------------------------
// Kernel 2: noise generation + perturbed top-8 counting, BOTH passes
// grid(64, NCHUNK, 2), block(256)=8 warps. z selects pass.
// One warp-sample covers rows bLow and bLow+64 (threefry counter pair).
// ---------------------------------------------------------------------------
__global__ void __launch_bounds__(256) noise_topk_kernel(
    uint32_t k0a, uint32_t k1a, uint32_t k0b, uint32_t k1b,
    float sig1, float sig2, int nPerChunk)
{
    __shared__ float sLow[BB], sHigh[BB];
    __shared__ int   sCnt[2 * KK * BB];     // [half][k][d]

    int which = blockIdx.z;
    const float* __restrict__ src = which ? g_tgt  : g_pred;
    int*         __restrict__ cnt = which ? g_cnt2 : g_cnt1;
    uint32_t k0 = which ? k0b : k0a;
    uint32_t k1 = which ? k1b : k1a;
    float sigma = which ? sig2 : sig1;

    int tid  = threadIdx.x;
    int bLow = blockIdx.x;

    if (tid < BB) {
        sLow[tid]  = src[bLow * BB + tid];
        sHigh[tid] = src[(bLow + 64) * BB + tid];
    }
    for (int i = tid; i < 2 * KK * BB; i += 256) sCnt[i] = 0;
    __syncthreads();

    int warp = tid >> 5, lane = tid & 31;
    float xL0 = sLow[lane],  xL1 = sLow[lane + 32],  xL2 = sLow[lane + 64],  xL3 = sLow[lane + 96];
    float xH0 = sHigh[lane], xH1 = sHigh[lane + 32], xH2 = sHigh[lane + 64], xH3 = sHigh[lane + 96];

    int nBegin = blockIdx.y * nPerChunk;
    int nEnd   = nBegin + nPerChunk;

    for (int n = nBegin + warp; n < nEnd; n += 8) {
        uint32_t c = (uint32_t)(bLow * (NSAMP * BB) + n * BB) + (uint32_t)lane;
        uint32_t r0, r1;
        uint32_t a0, a1, a2, a3, h0, h1, h2, h3;

        threefry2x32(k0, k1, c,       c + HALF_ELEMS,       r0, r1);
        a0 = perturb_key(xL0, r0, sigma);  h0 = perturb_key(xH0, r1, sigma);
        threefry2x32(k0, k1, c + 32u, c + HALF_ELEMS + 32u, r0, r1);
        a1 = perturb_key(xL1, r0, sigma);  h1 = perturb_key(xH1, r1, sigma);
        threefry2x32(k0, k1, c + 64u, c + HALF_ELEMS + 64u, r0, r1);
        a2 = perturb_key(xL2, r0, sigma);  h2 = perturb_key(xH2, r1, sigma);
        threefry2x32(k0, k1, c + 96u, c + HALF_ELEMS + 96u, r0, r1);
        a3 = perturb_key(xL3, r0, sigma);  h3 = perturb_key(xH3, r1, sigma);

        topk8_pair_accum(a0, a1, a2, a3, h0, h1, h2, h3, lane, sCnt);
    }
    __syncthreads();

    for (int i = tid; i < 2 * KK * BB; i += 256) {
        int half = i >> 10;              // 0 -> row bLow, 1 -> row bLow+64
        int rem  = i & 1023;             // k*128 + d
        int row  = bLow + (half << 6);
        int v = sCnt[i];
        if (v) atomicAdd(&cnt[row * (KK * BB) + rem], v);
    }
}

// ---------------------------------------------------------------------------
// Kernel 3/4: deterministic reduction
// loss = -sum(c1*c2*tgt) / (1000*1000*1024)
// ---------------------------------------------------------------------------
__global__ void __launch_bounds__(256) reduce1_kernel()
{
    __shared__ double sd[256];
    int b = blockIdx.x;
    double acc = 0.0;
    for (int i = threadIdx.x; i < KK * BB; i += 256) {
        int d = i & 127;
        acc += (double)g_cnt1[b * (KK * BB) + i] *
               (double)g_cnt2[b * (KK * BB) + i] *
               (double)g_tgt[b * BB + d];
    }
    sd[threadIdx.x] = acc;
    __syncthreads();
    for (int s = 128; s > 0; s >>= 1) {
        if (threadIdx.x < s) sd[threadIdx.x] += sd[threadIdx.x + s];
        __syncthreads();
    }
    if (threadIdx.x == 0) g_partial[b] = sd[0];
}

__global__ void __launch_bounds__(128) reduce2_kernel(float* __restrict__ out)
{
    __shared__ double sd[128];
    sd[threadIdx.x] = g_partial[threadIdx.x];
    __syncthreads();
    for (int s = 64; s > 0; s >>= 1) {
        if (threadIdx.x < s) sd[threadIdx.x] += sd[threadIdx.x + s];
        __syncthreads();
    }
    if (threadIdx.x == 0)
        out[0] = (float)(-sd[0] / (1000.0 * 1000.0 * (double)(KK * BB)));
}

// ---------------------------------------------------------------------------
// Launch
// ---------------------------------------------------------------------------
extern "C" void kernel_launch(void* const* d_in, const int* in_sizes, int n_in,
                              void* d_out, int out_size)
{
    (void)in_sizes; (void)n_in; (void)out_size;
    const float* cad   = (const float*)d_in[0];
    const float* scan  = (const float*)d_in[1];
    const float* sim   = (const float*)d_in[2];
    const int*   sidx  = (const int*)d_in[3];
    const int*   shidx = (const int*)d_in[4];
    float*       out   = (float*)d_out;

    // nk1, nk2 = jax.random.split(jax.random.key(42)); key(42) = (0, 42)
    uint32_t o00, o10, o01, o11;
    threefry2x32(0u, 42u, 0u, 2u, o00, o10);
    threefry2x32(0u, 42u, 1u, 3u, o01, o11);
    uint32_t nk1_0 = o00, nk1_1 = o01;
    uint32_t nk2_0 = o10, nk2_1 = o11;

    const float sig1 = 0.05f;
    const float sig2 = (float)(0.05 / 200.0);

    zero_counts_kernel<<<(BB * KK * BB + 255) / 256, 256>>>();
    prep_kernel<<<BB, 128>>>(cad, scan, sim, sidx, shidx);

    const int NCHUNK = 10;                 // 100 samples per chunk
    dim3 grid(64, NCHUNK, 2);
    noise_topk_kernel<<<grid, 256>>>(nk1_0, nk1_1, nk2_0, nk2_1,
                                     sig1, sig2, NSAMP / NCHUNK);

    reduce1_kernel<<<BB, 256>>>();
    reduce2_kernel<<<1, 128>>>(out);
}

// round 3
// speedup vs baseline: 2.2052x; 1.1807x over previous
#include <cuda_runtime.h>
#include <cstdint>

// ---------------------------------------------------------------------------
// Problem constants
// ---------------------------------------------------------------------------
#define BB     128          // batch
#define DD     256          // embedding dim
#define NSAMP  1000         // MC samples
#define KK     8            // top-k
#define NSHAPES 8000
#define HALF_ELEMS 8192000u // (128*1000*128)/2 -> row b pairs with row b+64

// ---------------------------------------------------------------------------
// Device scratch (no allocations allowed)
// ---------------------------------------------------------------------------
__device__ float  g_pred[BB * BB];
__device__ float  g_tgt [BB * BB];
__device__ int    g_cnt1[BB * KK * BB];   // pred-side indicator counts
__device__ int    g_cnt2[BB * KK * BB];   // tgt-side indicator counts
__device__ double g_partial[BB];

// ---------------------------------------------------------------------------
// threefry2x32 — exactly JAX's schedule
// ---------------------------------------------------------------------------
__host__ __device__ __forceinline__ void threefry2x32(
    uint32_t k0, uint32_t k1, uint32_t x0, uint32_t x1,
    uint32_t& o0, uint32_t& o1)
{
    uint32_t ks2 = k0 ^ k1 ^ 0x1BD11BDAu;
#define TF_ROUND(r) { x0 += x1; x1 = (x1 << (r)) | (x1 >> (32 - (r))); x1 ^= x0; }
    x0 += k0; x1 += k1;
    TF_ROUND(13) TF_ROUND(15) TF_ROUND(26) TF_ROUND(6)
    x0 += k1;  x1 += ks2 + 1u;
    TF_ROUND(17) TF_ROUND(29) TF_ROUND(16) TF_ROUND(24)
    x0 += ks2; x1 += k0 + 2u;
    TF_ROUND(13) TF_ROUND(15) TF_ROUND(26) TF_ROUND(6)
    x0 += k0;  x1 += k1 + 3u;
    TF_ROUND(17) TF_ROUND(29) TF_ROUND(16) TF_ROUND(24)
    x0 += k1;  x1 += ks2 + 4u;
    TF_ROUND(13) TF_ROUND(15) TF_ROUND(26) TF_ROUND(6)
    x0 += ks2; x1 += k0 + 5u;
#undef TF_ROUND
    o0 = x0; o1 = x1;
}

// ---------------------------------------------------------------------------
// bits -> N(0,1) exactly like jax.random.normal (uniform bit-trick + XLA ErfInv32)
// ---------------------------------------------------------------------------
__device__ __forceinline__ float jx_normal(uint32_t bits)
{
    float f = __uint_as_float((bits >> 9) | 0x3f800000u) - 1.0f;   // [0,1)
    const float lo = -0.99999994f;                                  // nextafter(-1,0)
    float u = __fadd_rn(__fmul_rn(f, 2.0f), lo);
    u = fmaxf(u, lo);

    float w = -log1pf(-__fmul_rn(u, u));
    float p;
    if (w < 5.0f) {
        w -= 2.5f;
        p = 2.81022636e-08f;
        p = fmaf(p, w,  3.43273939e-07f);
        p = fmaf(p, w, -3.5233877e-06f);
        p = fmaf(p, w, -4.39150654e-06f);
        p = fmaf(p, w,  0.00021858087f);
        p = fmaf(p, w, -0.00125372503f);
        p = fmaf(p, w, -0.00417768164f);
        p = fmaf(p, w,  0.246640727f);
        p = fmaf(p, w,  1.50140941f);
    } else {
        w = sqrtf(w) - 3.0f;
        p = -0.000200214257f;
        p = fmaf(p, w,  0.000100950558f);
        p = fmaf(p, w,  0.00134934322f);
        p = fmaf(p, w, -0.00367342844f);
        p = fmaf(p, w,  0.00573950773f);
        p = fmaf(p, w, -0.0076224613f);
        p = fmaf(p, w,  0.00943887047f);
        p = fmaf(p, w,  1.00167406f);
        p = fmaf(p, w,  2.83297682f);
    }
    return __fmul_rn(1.41421354f, __fmul_rn(p, u));   // sqrt(2)*erfinv(u)
}

// perturbed value -> packed sort key:
//   top 25 bits = order-isomorphic float map, low 7 bits = (127 - idx)
// so one unsigned max gives winner with lowest-index tie-break.
__device__ __forceinline__ uint32_t perturb_pack(float x, uint32_t bits, float sigma,
                                                 uint32_t invidx)
{
    float v = __fadd_rn(x, __fmul_rn(sigma, jx_normal(bits)));
    uint32_t b = __float_as_uint(v);
    uint32_t key = b ^ ((uint32_t)((int32_t)b >> 31) | 0x80000000u);
    return (key & 0xFFFFFF80u) | invidx;
}

// ---------------------------------------------------------------------------
// Tournament top-8 over 128 packed keys (4/lane, one per quarter),
// both halves interleaved for ILP. Winner mask reconstructed via ballots,
// ranks via n-th-set-bit search. Counts into shared counters.
// ---------------------------------------------------------------------------
#define SWAPD(a,b) { uint32_t t_ = (a) < (b) ? (b) : (a); (b) = (a) < (b) ? (a) : (b); (a) = t_; }

__device__ __forceinline__ void topk8_pair_accum(
    uint32_t a0, uint32_t a1, uint32_t a2, uint32_t a3,
    uint32_t b0, uint32_t b1, uint32_t b2, uint32_t b3,
    int lane, int* __restrict__ scnt)
{
    // per-lane descending sort of 4 packed keys (index rides inside)
    SWAPD(a0,a1) SWAPD(a2,a3) SWAPD(a0,a2) SWAPD(a1,a3) SWAPD(a1,a2)
    SWAPD(b0,b1) SWAPD(b2,b3) SWAPD(b0,b2) SWAPD(b1,b3) SWAPD(b1,b2)

    uint32_t wonA = 0, wonB = 0;

#pragma unroll
    for (int r = 0; r < 8; ++r) {
        uint32_t mA = __reduce_max_sync(0xffffffffu, a0);
        uint32_t mB = __reduce_max_sync(0xffffffffu, b0);
        bool winA = (a0 == mA);           // unique: low 7 bits are a global id
        bool winB = (b0 == mB);
        if (winA) {
            wonA |= 1u << (3u - ((a0 & 127u) >> 5));   // quarter of winning index
            a0 = a1; a1 = a2; a2 = a3; a3 = 0u;
        }
        if (winB) {
            wonB |= 1u << (3u - ((b0 & 127u) >> 5));
            b0 = b1; b1 = b2; b2 = b3; b3 = 0u;
        }
    }

    // winner bitmask per quarter: bit L of mq <=> index q*32+L is a winner
    uint32_t A0 = __ballot_sync(0xffffffffu,  wonA & 1u);
    uint32_t A1 = __ballot_sync(0xffffffffu, (wonA >> 1) & 1u);
    uint32_t A2 = __ballot_sync(0xffffffffu, (wonA >> 2) & 1u);
    uint32_t A3 = __ballot_sync(0xffffffffu, (wonA >> 3) & 1u);
    uint32_t B0 = __ballot_sync(0xffffffffu,  wonB & 1u);
    uint32_t B1 = __ballot_sync(0xffffffffu, (wonB >> 1) & 1u);
    uint32_t B2 = __ballot_sync(0xffffffffu, (wonB >> 2) & 1u);
    uint32_t B3 = __ballot_sync(0xffffffffu, (wonB >> 3) & 1u);

    // lanes 0-7: rank r of half A; lanes 8-15: rank r of half B
    int r = lane & 7;
    bool hB = (lane & 8) != 0;
    uint32_t w0 = hB ? B0 : A0, w1 = hB ? B1 : A1, w2 = hB ? B2 : A2, w3 = hB ? B3 : A3;

    int c0 = __popc(w0);
    int c01 = c0 + __popc(w1);
    int c012 = c01 + __popc(w2);
    uint32_t word = w0; int base = 0, n = r;
    if (r >= c0)   { word = w1; base = 32; n = r - c0; }
    if (r >= c01)  { word = w2; base = 64; n = r - c01; }
    if (r >= c012) { word = w3; base = 96; n = r - c012; }

    // n-th (0-based) set bit of word
    unsigned pos = 0, c;
    c = __popc(word & 0xFFFFu); if ((unsigned)n >= c) { n -= c; pos += 16; word >>= 16; }
    c = __popc(word & 0xFFu);   if ((unsigned)n >= c) { n -= c; pos += 8;  word >>= 8; }
    c = __popc(word & 0xFu);    if ((unsigned)n >= c) { n -= c; pos += 4;  word >>= 4; }
    c = __popc(word & 0x3u);    if ((unsigned)n >= c) { n -= c; pos += 2;  word >>= 2; }
    c = word & 1u;              if ((unsigned)n >= c) { pos += 1; }

    int idx = base + (int)pos;
    if (lane < 16)
        atomicAdd(&scnt[((lane >> 3) * (KK * BB)) + r * BB + idx], 1);
}

// ---------------------------------------------------------------------------
// Kernel 0: zero count arrays
// ---------------------------------------------------------------------------
__global__ void zero_counts_kernel()
{
    int i = blockIdx.x * blockDim.x + threadIdx.x;
    if (i < BB * KK * BB) { g_cnt1[i] = 0; g_cnt2[i] = 0; }
}

// ---------------------------------------------------------------------------
// Kernel 1: pred_sim = scan @ cad^T ; tgt_sim gather
// ---------------------------------------------------------------------------
__global__ void __launch_bounds__(128) prep_kernel(
    const float* __restrict__ cad, const float* __restrict__ scan,
    const float* __restrict__ sim, const int* __restrict__ scannet_idx,
    const int* __restrict__ shapenet_idx)
{
    __shared__ float row[DD];
    int i = blockIdx.x, j = threadIdx.x;
    row[j]       = scan[i * DD + j];
    row[j + 128] = scan[i * DD + 128 + j];
    __syncthreads();

    const float4* c4 = reinterpret_cast<const float4*>(cad + (size_t)j * DD);
    float acc = 0.0f;
#pragma unroll 8
    for (int t = 0; t < DD / 4; ++t) {
        float4 v = c4[t];
        acc = fmaf(row[4 * t + 0], v.x, acc);
        acc = fmaf(row[4 * t + 1], v.y, acc);
        acc = fmaf(row[4 * t + 2], v.z, acc);
        acc = fmaf(row[4 * t + 3], v.w, acc);
    }
    g_pred[i * BB + j] = acc;
    g_tgt[i * BB + j]  = sim[(size_t)scannet_idx[i] * NSHAPES + shapenet_idx[j]];
}

// ---------------------------------------------------------------------------
// Kernel 2: noise generation + perturbed top-8 counting, BOTH passes
// grid(64, NCHUNK, 2), block(256)=8 warps. z selects pass.
// One warp-sample covers rows bLow and bLow+64 (threefry counter pair).
// ---------------------------------------------------------------------------
__global__ void __launch_bounds__(256) noise_topk_kernel(
    uint32_t k0a, uint32_t k1a, uint32_t k0b, uint32_t k1b,
    float sig1, float sig2, int nPerChunk)
{
    __shared__ float sLow[BB], sHigh[BB];
    __shared__ int   sCnt[2 * KK * BB];     // [half][k][d]

    int which = blockIdx.z;
    const float* __restrict__ src = which ? g_tgt  : g_pred;
    int*         __restrict__ cnt = which ? g_cnt2 : g_cnt1;
    uint32_t k0 = which ? k0b : k0a;
    uint32_t k1 = which ? k1b : k1a;
    float sigma = which ? sig2 : sig1;

    int tid  = threadIdx.x;
    int bLow = blockIdx.x;

    if (tid < BB) {
        sLow[tid]  = src[bLow * BB + tid];
        sHigh[tid] = src[(bLow + 64) * BB + tid];
    }
    for (int i = tid; i < 2 * KK * BB; i += 256) sCnt[i] = 0;
    __syncthreads();

    int warp = tid >> 5, lane = tid & 31;
    float xL0 = sLow[lane],  xL1 = sLow[lane + 32],  xL2 = sLow[lane + 64],  xL3 = sLow[lane + 96];
    float xH0 = sHigh[lane], xH1 = sHigh[lane + 32], xH2 = sHigh[lane + 64], xH3 = sHigh[lane + 96];

    uint32_t inv0 = 127u - (uint32_t)lane;   // invidx for slot q: 127 - (q*32+lane)
    uint32_t inv1 = 95u  - (uint32_t)lane;
    uint32_t inv2 = 63u  - (uint32_t)lane;
    uint32_t inv3 = 31u  - (uint32_t)lane;

    int nBegin = blockIdx.y * nPerChunk;
    int nEnd   = nBegin + nPerChunk;

    for (int n = nBegin + warp; n < nEnd; n += 8) {
        uint32_t c = (uint32_t)(bLow * (NSAMP * BB) + n * BB) + (uint32_t)lane;
        uint32_t r0, r1;
        uint32_t a0, a1, a2, a3, h0, h1, h2, h3;

        threefry2x32(k0, k1, c,       c + HALF_ELEMS,       r0, r1);
        a0 = perturb_pack(xL0, r0, sigma, inv0);  h0 = perturb_pack(xH0, r1, sigma, inv0);
        threefry2x32(k0, k1, c + 32u, c + HALF_ELEMS + 32u, r0, r1);
        a1 = perturb_pack(xL1, r0, sigma, inv1);  h1 = perturb_pack(xH1, r1, sigma, inv1);
        threefry2x32(k0, k1, c + 64u, c + HALF_ELEMS + 64u, r0, r1);
        a2 = perturb_pack(xL2, r0, sigma, inv2);  h2 = perturb_pack(xH2, r1, sigma, inv2);
        threefry2x32(k0, k1, c + 96u, c + HALF_ELEMS + 96u, r0, r1);
        a3 = perturb_pack(xL3, r0, sigma, inv3);  h3 = perturb_pack(xH3, r1, sigma, inv3);

        topk8_pair_accum(a0, a1, a2, a3, h0, h1, h2, h3, lane, sCnt);
    }
    __syncthreads();

    for (int i = tid; i < 2 * KK * BB; i += 256) {
        int half = i >> 10;              // 0 -> row bLow, 1 -> row bLow+64
        int rem  = i & 1023;             // k*128 + d
        int row  = bLow + (half << 6);
        int v = sCnt[i];
        if (v) atomicAdd(&cnt[row * (KK * BB) + rem], v);
    }
}

// ---------------------------------------------------------------------------
// Kernel 3/4: deterministic reduction
// loss = -sum(c1*c2*tgt) / (1000*1000*1024)
// ---------------------------------------------------------------------------
__global__ void __launch_bounds__(256) reduce1_kernel()
{
    __shared__ double sd[256];
    int b = blockIdx.x;
    double acc = 0.0;
    for (int i = threadIdx.x; i < KK * BB; i += 256) {
        int d = i & 127;
        acc += (double)g_cnt1[b * (KK * BB) + i] *
               (double)g_cnt2[b * (KK * BB) + i] *
               (double)g_tgt[b * BB + d];
    }
    sd[threadIdx.x] = acc;
    __syncthreads();
    for (int s = 128; s > 0; s >>= 1) {
        if (threadIdx.x < s) sd[threadIdx.x] += sd[threadIdx.x + s];
        __syncthreads();
    }
    if (threadIdx.x == 0) g_partial[b] = sd[0];
}

__global__ void __launch_bounds__(128) reduce2_kernel(float* __restrict__ out)
{
    __shared__ double sd[128];
    sd[threadIdx.x] = g_partial[threadIdx.x];
    __syncthreads();
    for (int s = 64; s > 0; s >>= 1) {
        if (threadIdx.x < s) sd[threadIdx.x] += sd[threadIdx.x + s];
        __syncthreads();
    }
    if (threadIdx.x == 0)
        out[0] = (float)(-sd[0] / (1000.0 * 1000.0 * (double)(KK * BB)));
}

// ---------------------------------------------------------------------------
// Launch
// ---------------------------------------------------------------------------
extern "C" void kernel_launch(void* const* d_in, const int* in_sizes, int n_in,
                              void* d_out, int out_size)
{
    (void)in_sizes; (void)n_in; (void)out_size;
    const float* cad   = (const float*)d_in[0];
    const float* scan  = (const float*)d_in[1];
    const float* sim   = (const float*)d_in[2];
    const int*   sidx  = (const int*)d_in[3];
    const int*   shidx = (const int*)d_in[4];
    float*       out   = (float*)d_out;

    // nk1, nk2 = jax.random.split(jax.random.key(42)); key(42) = (0, 42)
    uint32_t o00, o10, o01, o11;
    threefry2x32(0u, 42u, 0u, 2u, o00, o10);
    threefry2x32(0u, 42u, 1u, 3u, o01, o11);
    uint32_t nk1_0 = o00, nk1_1 = o01;
    uint32_t nk2_0 = o10, nk2_1 = o11;

    const float sig1 = 0.05f;
    const float sig2 = (float)(0.05 / 200.0);

    zero_counts_kernel<<<(BB * KK * BB + 255) / 256, 256>>>();
    prep_kernel<<<BB, 128>>>(cad, scan, sim, sidx, shidx);

    const int NCHUNK = 10;                 // 100 samples per chunk
    dim3 grid(64, NCHUNK, 2);
    noise_topk_kernel<<<grid, 256>>>(nk1_0, nk1_1, nk2_0, nk2_1,
                                     sig1, sig2, NSAMP / NCHUNK);

    reduce1_kernel<<<BB, 256>>>();
    reduce2_kernel<<<1, 128>>>(out);
}

// round 4
// speedup vs baseline: 2.5504x; 1.1565x over previous
#include <cuda_runtime.h>
#include <cstdint>

// ---------------------------------------------------------------------------
// Problem constants
// ---------------------------------------------------------------------------
#define BB     128          // batch
#define DD     256          // embedding dim
#define NSAMP  1000         // MC samples
#define KK     8            // top-k
#define NSHAPES 8000
#define HALF_ELEMS 8192000u // (128*1000*128)/2 -> row b pairs with row b+64

// ---------------------------------------------------------------------------
// Device scratch (no allocations allowed)
// ---------------------------------------------------------------------------
__device__ float  g_pred[BB * BB];
__device__ float  g_tgt [BB * BB];
__device__ int    g_cnt1[BB * KK * BB];   // pred-side indicator counts
__device__ int    g_cnt2[BB * KK * BB];   // tgt-side indicator counts
__device__ float  g_partialf[16];

// ---------------------------------------------------------------------------
// threefry2x32 — exactly JAX's schedule
// ---------------------------------------------------------------------------
__host__ __device__ __forceinline__ void threefry2x32(
    uint32_t k0, uint32_t k1, uint32_t x0, uint32_t x1,
    uint32_t& o0, uint32_t& o1)
{
    uint32_t ks2 = k0 ^ k1 ^ 0x1BD11BDAu;
#define TF_ROUND(r) { x0 += x1; x1 = (x1 << (r)) | (x1 >> (32 - (r))); x1 ^= x0; }
    x0 += k0; x1 += k1;
    TF_ROUND(13) TF_ROUND(15) TF_ROUND(26) TF_ROUND(6)
    x0 += k1;  x1 += ks2 + 1u;
    TF_ROUND(17) TF_ROUND(29) TF_ROUND(16) TF_ROUND(24)
    x0 += ks2; x1 += k0 + 2u;
    TF_ROUND(13) TF_ROUND(15) TF_ROUND(26) TF_ROUND(6)
    x0 += k0;  x1 += k1 + 3u;
    TF_ROUND(17) TF_ROUND(29) TF_ROUND(16) TF_ROUND(24)
    x0 += k1;  x1 += ks2 + 4u;
    TF_ROUND(13) TF_ROUND(15) TF_ROUND(26) TF_ROUND(6)
    x0 += ks2; x1 += k0 + 5u;
#undef TF_ROUND
    o0 = x0; o1 = x1;
}

// ---------------------------------------------------------------------------
// bits -> N(0,1): JAX uniform bit-trick + XLA ErfInv32 polynomial, with the
// log1p replaced by a single-rounded fmaf + MUFU-based __logf. Error vs the
// exact path is below the 2^-25 key-truncation granule in all regimes that
// can affect ordering.
// ---------------------------------------------------------------------------
__device__ __forceinline__ float jx_normal(uint32_t bits)
{
    float f = __uint_as_float((bits >> 9) | 0x3f800000u) - 1.0f;   // [0,1)
    const float lo = -0.99999994f;                                  // nextafter(-1,0)
    float u = __fadd_rn(__fmul_rn(f, 2.0f), lo);
    u = fmaxf(u, lo);

    float w = -__logf(fmaf(-u, u, 1.0f));     // ~= -log1p(-u*u)
    float p;
    if (w < 5.0f) {
        w -= 2.5f;
        p = 2.81022636e-08f;
        p = fmaf(p, w,  3.43273939e-07f);
        p = fmaf(p, w, -3.5233877e-06f);
        p = fmaf(p, w, -4.39150654e-06f);
        p = fmaf(p, w,  0.00021858087f);
        p = fmaf(p, w, -0.00125372503f);
        p = fmaf(p, w, -0.00417768164f);
        p = fmaf(p, w,  0.246640727f);
        p = fmaf(p, w,  1.50140941f);
    } else {
        w = sqrtf(w) - 3.0f;
        p = -0.000200214257f;
        p = fmaf(p, w,  0.000100950558f);
        p = fmaf(p, w,  0.00134934322f);
        p = fmaf(p, w, -0.00367342844f);
        p = fmaf(p, w,  0.00573950773f);
        p = fmaf(p, w, -0.0076224613f);
        p = fmaf(p, w,  0.00943887047f);
        p = fmaf(p, w,  1.00167406f);
        p = fmaf(p, w,  2.83297682f);
    }
    return __fmul_rn(1.41421354f, __fmul_rn(p, u));   // sqrt(2)*erfinv(u)
}

// perturbed value -> packed sort key:
//   top 25 bits = order-isomorphic float map, low 7 bits = (127 - idx)
__device__ __forceinline__ uint32_t perturb_pack(float x, uint32_t bits, float sigma,
                                                 uint32_t invidx)
{
    float v = __fadd_rn(x, __fmul_rn(sigma, jx_normal(bits)));
    uint32_t b = __float_as_uint(v);
    uint32_t key = b ^ ((uint32_t)((int32_t)b >> 31) | 0x80000000u);
    return (key & 0xFFFFFF80u) | invidx;
}

// ---------------------------------------------------------------------------
// Tournament top-8 over 128 packed keys (4/lane, one per quarter),
// both halves interleaved for ILP. Winner mask via ballots, ranks via
// n-th-set-bit search. Counts into shared counters.
// ---------------------------------------------------------------------------
#define SWAPD(a,b) { uint32_t t_ = (a) < (b) ? (b) : (a); (b) = (a) < (b) ? (a) : (b); (a) = t_; }

__device__ __forceinline__ void topk8_pair_accum(
    uint32_t a0, uint32_t a1, uint32_t a2, uint32_t a3,
    uint32_t b0, uint32_t b1, uint32_t b2, uint32_t b3,
    int lane, int* __restrict__ scnt)
{
    // per-lane descending sort of 4 packed keys (index rides inside)
    SWAPD(a0,a1) SWAPD(a2,a3) SWAPD(a0,a2) SWAPD(a1,a3) SWAPD(a1,a2)
    SWAPD(b0,b1) SWAPD(b2,b3) SWAPD(b0,b2) SWAPD(b1,b3) SWAPD(b1,b2)

    uint32_t wonA = 0, wonB = 0;

#pragma unroll
    for (int r = 0; r < 8; ++r) {
        uint32_t mA = __reduce_max_sync(0xffffffffu, a0);
        uint32_t mB = __reduce_max_sync(0xffffffffu, b0);
        bool winA = (a0 == mA);           // unique: low 7 bits are a global id
        bool winB = (b0 == mB);
        if (winA) {
            wonA |= 1u << (3u - ((a0 & 127u) >> 5));   // quarter of winning index
            a0 = a1; a1 = a2; a2 = a3; a3 = 0u;
        }
        if (winB) {
            wonB |= 1u << (3u - ((b0 & 127u) >> 5));
            b0 = b1; b1 = b2; b2 = b3; b3 = 0u;
        }
    }

    // winner bitmask per quarter: bit L of mq <=> index q*32+L is a winner
    uint32_t A0 = __ballot_sync(0xffffffffu,  wonA & 1u);
    uint32_t A1 = __ballot_sync(0xffffffffu, (wonA >> 1) & 1u);
    uint32_t A2 = __ballot_sync(0xffffffffu, (wonA >> 2) & 1u);
    uint32_t A3 = __ballot_sync(0xffffffffu, (wonA >> 3) & 1u);
    uint32_t B0 = __ballot_sync(0xffffffffu,  wonB & 1u);
    uint32_t B1 = __ballot_sync(0xffffffffu, (wonB >> 1) & 1u);
    uint32_t B2 = __ballot_sync(0xffffffffu, (wonB >> 2) & 1u);
    uint32_t B3 = __ballot_sync(0xffffffffu, (wonB >> 3) & 1u);

    // lanes 0-7: rank r of half A; lanes 8-15: rank r of half B
    int r = lane & 7;
    bool hB = (lane & 8) != 0;
    uint32_t w0 = hB ? B0 : A0, w1 = hB ? B1 : A1, w2 = hB ? B2 : A2, w3 = hB ? B3 : A3;

    int c0 = __popc(w0);
    int c01 = c0 + __popc(w1);
    int c012 = c01 + __popc(w2);
    uint32_t word = w0; int base = 0, n = r;
    if (r >= c0)   { word = w1; base = 32; n = r - c0; }
    if (r >= c01)  { word = w2; base = 64; n = r - c01; }
    if (r >= c012) { word = w3; base = 96; n = r - c012; }

    // n-th (0-based) set bit of word
    unsigned pos = 0, c;
    c = __popc(word & 0xFFFFu); if ((unsigned)n >= c) { n -= c; pos += 16; word >>= 16; }
    c = __popc(word & 0xFFu);   if ((unsigned)n >= c) { n -= c; pos += 8;  word >>= 8; }
    c = __popc(word & 0xFu);    if ((unsigned)n >= c) { n -= c; pos += 4;  word >>= 4; }
    c = __popc(word & 0x3u);    if ((unsigned)n >= c) { n -= c; pos += 2;  word >>= 2; }
    c = word & 1u;              if ((unsigned)n >= c) { pos += 1; }

    int idx = base + (int)pos;
    if (lane < 16)
        atomicAdd(&scnt[((lane >> 3) * (KK * BB)) + r * BB + idx], 1);
}

// ---------------------------------------------------------------------------
// Kernel 1: pred_sim = scan @ cad^T ; tgt_sim gather ; zero counters
// ---------------------------------------------------------------------------
__global__ void __launch_bounds__(128) prep_kernel(
    const float* __restrict__ cad, const float* __restrict__ scan,
    const float* __restrict__ sim, const int* __restrict__ scannet_idx,
    const int* __restrict__ shapenet_idx)
{
    __shared__ float row[DD];
    int i = blockIdx.x, j = threadIdx.x;
    row[j]       = scan[i * DD + j];
    row[j + 128] = scan[i * DD + 128 + j];

    // zero 8 counter ints in each array per thread (covers BB*KK*BB total)
    {
        int t = (i * 128 + j) * 2;   // int4 index
        int4 z = make_int4(0, 0, 0, 0);
        reinterpret_cast<int4*>(g_cnt1)[t]     = z;
        reinterpret_cast<int4*>(g_cnt1)[t + 1] = z;
        reinterpret_cast<int4*>(g_cnt2)[t]     = z;
        reinterpret_cast<int4*>(g_cnt2)[t + 1] = z;
    }
    __syncthreads();

    const float4* c4 = reinterpret_cast<const float4*>(cad + (size_t)j * DD);
    float acc = 0.0f;
#pragma unroll 8
    for (int t = 0; t < DD / 4; ++t) {
        float4 v = c4[t];
        acc = fmaf(row[4 * t + 0], v.x, acc);
        acc = fmaf(row[4 * t + 1], v.y, acc);
        acc = fmaf(row[4 * t + 2], v.z, acc);
        acc = fmaf(row[4 * t + 3], v.w, acc);
    }
    g_pred[i * BB + j] = acc;
    g_tgt[i * BB + j]  = sim[(size_t)scannet_idx[i] * NSHAPES + shapenet_idx[j]];
}

// ---------------------------------------------------------------------------
// Kernel 2: noise generation + perturbed top-8 counting, BOTH passes
// grid(64, NCHUNK, 2), block(256)=8 warps. z selects pass.
// One warp-sample covers rows bLow and bLow+64 (threefry counter pair).
// ---------------------------------------------------------------------------
__global__ void __launch_bounds__(256, 6) noise_topk_kernel(
    uint32_t k0a, uint32_t k1a, uint32_t k0b, uint32_t k1b,
    float sig1, float sig2, int nPerChunk)
{
    __shared__ float sLow[BB], sHigh[BB];
    __shared__ int   sCnt[2 * KK * BB];     // [half][k][d]

    int which = blockIdx.z;
    const float* __restrict__ src = which ? g_tgt  : g_pred;
    int*         __restrict__ cnt = which ? g_cnt2 : g_cnt1;
    uint32_t k0 = which ? k0b : k0a;
    uint32_t k1 = which ? k1b : k1a;
    float sigma = which ? sig2 : sig1;

    int tid  = threadIdx.x;
    int bLow = blockIdx.x;

    if (tid < BB) {
        sLow[tid]  = src[bLow * BB + tid];
        sHigh[tid] = src[(bLow + 64) * BB + tid];
    }
    for (int i = tid; i < 2 * KK * BB; i += 256) sCnt[i] = 0;
    __syncthreads();

    int warp = tid >> 5, lane = tid & 31;
    float xL0 = sLow[lane],  xL1 = sLow[lane + 32],  xL2 = sLow[lane + 64],  xL3 = sLow[lane + 96];
    float xH0 = sHigh[lane], xH1 = sHigh[lane + 32], xH2 = sHigh[lane + 64], xH3 = sHigh[lane + 96];

    uint32_t inv0 = 127u - (uint32_t)lane;   // invidx for slot q: 127 - (q*32+lane)
    uint32_t inv1 = 95u  - (uint32_t)lane;
    uint32_t inv2 = 63u  - (uint32_t)lane;
    uint32_t inv3 = 31u  - (uint32_t)lane;

    int nBegin = blockIdx.y * nPerChunk;
    int nEnd   = nBegin + nPerChunk;

    for (int n = nBegin + warp; n < nEnd; n += 8) {
        uint32_t c = (uint32_t)(bLow * (NSAMP * BB) + n * BB) + (uint32_t)lane;
        uint32_t r0, r1;
        uint32_t a0, a1, a2, a3, h0, h1, h2, h3;

        threefry2x32(k0, k1, c,       c + HALF_ELEMS,       r0, r1);
        a0 = perturb_pack(xL0, r0, sigma, inv0);  h0 = perturb_pack(xH0, r1, sigma, inv0);
        threefry2x32(k0, k1, c + 32u, c + HALF_ELEMS + 32u, r0, r1);
        a1 = perturb_pack(xL1, r0, sigma, inv1);  h1 = perturb_pack(xH1, r1, sigma, inv1);
        threefry2x32(k0, k1, c + 64u, c + HALF_ELEMS + 64u, r0, r1);
        a2 = perturb_pack(xL2, r0, sigma, inv2);  h2 = perturb_pack(xH2, r1, sigma, inv2);
        threefry2x32(k0, k1, c + 96u, c + HALF_ELEMS + 96u, r0, r1);
        a3 = perturb_pack(xL3, r0, sigma, inv3);  h3 = perturb_pack(xH3, r1, sigma, inv3);

        topk8_pair_accum(a0, a1, a2, a3, h0, h1, h2, h3, lane, sCnt);
    }
    __syncthreads();

    for (int i = tid; i < 2 * KK * BB; i += 256) {
        int half = i >> 10;              // 0 -> row bLow, 1 -> row bLow+64
        int rem  = i & 1023;             // k*128 + d
        int row  = bLow + (half << 6);
        int v = sCnt[i];
        if (v) atomicAdd(&cnt[row * (KK * BB) + rem], v);
    }
}

// ---------------------------------------------------------------------------
// Kernel 3/4: deterministic reduction
// loss = -sum(c1*c2*tgt) / (1000*1000*1024)
// c1*c2 <= 1e6 is exact in int32; accumulate fp32 (reference is fp32 anyway),
// fixed order -> deterministic.
// ---------------------------------------------------------------------------
__global__ void __launch_bounds__(256) reduce1_kernel()
{
    // 16 blocks x 8 warps: one warp per batch row
    int b    = blockIdx.x * 8 + (threadIdx.x >> 5);
    int lane = threadIdx.x & 31;
    const int base = b * (KK * BB);
    float acc = 0.0f;
#pragma unroll
    for (int i = lane; i < KK * BB; i += 32) {
        int prod = g_cnt1[base + i] * g_cnt2[base + i];
        acc = fmaf((float)prod, g_tgt[b * BB + (i & 127)], acc);
    }
#pragma unroll
    for (int off = 16; off > 0; off >>= 1)
        acc += __shfl_xor_sync(0xffffffffu, acc, off);

    __shared__ float sw[8];
    if (lane == 0) sw[threadIdx.x >> 5] = acc;
    __syncthreads();
    if (threadIdx.x < 8) {
        float v = sw[threadIdx.x];
#pragma unroll
        for (int off = 4; off > 0; off >>= 1)
            v += __shfl_xor_sync(0xffu, v, off);
        if (threadIdx.x == 0) g_partialf[blockIdx.x] = v;
    }
}

__global__ void __launch_bounds__(32) reduce2_kernel(float* __restrict__ out)
{
    float v = (threadIdx.x < 16) ? g_partialf[threadIdx.x] : 0.0f;
#pragma unroll
    for (int off = 16; off > 0; off >>= 1)
        v += __shfl_xor_sync(0xffffffffu, v, off);
    if (threadIdx.x == 0)
        out[0] = -v / (1000.0f * 1000.0f * (float)(KK * BB));
}

// ---------------------------------------------------------------------------
// Launch
// ---------------------------------------------------------------------------
extern "C" void kernel_launch(void* const* d_in, const int* in_sizes, int n_in,
                              void* d_out, int out_size)
{
    (void)in_sizes; (void)n_in; (void)out_size;
    const float* cad   = (const float*)d_in[0];
    const float* scan  = (const float*)d_in[1];
    const float* sim   = (const float*)d_in[2];
    const int*   sidx  = (const int*)d_in[3];
    const int*   shidx = (const int*)d_in[4];
    float*       out   = (float*)d_out;

    // nk1, nk2 = jax.random.split(jax.random.key(42)); key(42) = (0, 42)
    uint32_t o00, o10, o01, o11;
    threefry2x32(0u, 42u, 0u, 2u, o00, o10);
    threefry2x32(0u, 42u, 1u, 3u, o01, o11);
    uint32_t nk1_0 = o00, nk1_1 = o01;
    uint32_t nk2_0 = o10, nk2_1 = o11;

    const float sig1 = 0.05f;
    const float sig2 = (float)(0.05 / 200.0);

    prep_kernel<<<BB, 128>>>(cad, scan, sim, sidx, shidx);

    const int NCHUNK = 10;                 // 100 samples per chunk
    dim3 grid(64, NCHUNK, 2);
    noise_topk_kernel<<<grid, 256>>>(nk1_0, nk1_1, nk2_0, nk2_1,
                                     sig1, sig2, NSAMP / NCHUNK);

    reduce1_kernel<<<16, 256>>>();
    reduce2_kernel<<<1, 32>>>(out);
}

// round 5
// speedup vs baseline: 6.0257x; 2.3627x over previous
#include <cuda_runtime.h>
#include <cstdint>

// ---------------------------------------------------------------------------
// Problem constants
// ---------------------------------------------------------------------------
#define BB     128          // batch
#define DD     256          // embedding dim
#define NSAMP  1000         // MC samples
#define KK     8            // top-k
#define NSHAPES 8000
#define HALF_ELEMS 8192000u // (128*1000*128)/2 -> element pairing offset
#define MAXC   16           // candidate cap per row (overflow -> fallback)

// ---------------------------------------------------------------------------
// Device scratch (no allocations allowed)
// ---------------------------------------------------------------------------
__device__ float  g_pred[BB * BB];
__device__ float  g_tgt [BB * BB];
__device__ int    g_cnt1[BB * KK * BB];   // pred-side indicator counts
__device__ int    g_cnt2[BB * KK * BB];   // tgt-side indicator counts
__device__ float  g_cval[2 * BB * MAXC];  // candidate base values
__device__ int    g_cidx[2 * BB * MAXC];  // candidate global indices (ascending)
__device__ int    g_cm  [2 * BB];         // candidate counts
__device__ int    g_over[2 * BB];         // overflow flags (m > MAXC)
__device__ float  g_partialf[128];

// ---------------------------------------------------------------------------
// threefry2x32 — exactly JAX's schedule
// ---------------------------------------------------------------------------
__host__ __device__ __forceinline__ void threefry2x32(
    uint32_t k0, uint32_t k1, uint32_t x0, uint32_t x1,
    uint32_t& o0, uint32_t& o1)
{
    uint32_t ks2 = k0 ^ k1 ^ 0x1BD11BDAu;
#define TF_ROUND(r) { x0 += x1; x1 = (x1 << (r)) | (x1 >> (32 - (r))); x1 ^= x0; }
    x0 += k0; x1 += k1;
    TF_ROUND(13) TF_ROUND(15) TF_ROUND(26) TF_ROUND(6)
    x0 += k1;  x1 += ks2 + 1u;
    TF_ROUND(17) TF_ROUND(29) TF_ROUND(16) TF_ROUND(24)
    x0 += ks2; x1 += k0 + 2u;
    TF_ROUND(13) TF_ROUND(15) TF_ROUND(26) TF_ROUND(6)
    x0 += k0;  x1 += k1 + 3u;
    TF_ROUND(17) TF_ROUND(29) TF_ROUND(16) TF_ROUND(24)
    x0 += k1;  x1 += ks2 + 4u;
    TF_ROUND(13) TF_ROUND(15) TF_ROUND(26) TF_ROUND(6)
    x0 += ks2; x1 += k0 + 5u;
#undef TF_ROUND
    o0 = x0; o1 = x1;
}

// ---------------------------------------------------------------------------
// bits -> N(0,1): JAX uniform bit-trick + XLA ErfInv32 polynomial (fast log).
// |result| <= ~5.43 always (bounded support of the bit-trick uniform).
// ---------------------------------------------------------------------------
__device__ __forceinline__ float jx_normal(uint32_t bits)
{
    float f = __uint_as_float((bits >> 9) | 0x3f800000u) - 1.0f;   // [0,1)
    const float lo = -0.99999994f;                                  // nextafter(-1,0)
    float u = __fadd_rn(__fmul_rn(f, 2.0f), lo);
    u = fmaxf(u, lo);

    float w = -__logf(fmaf(-u, u, 1.0f));     // ~= -log1p(-u*u)
    float p;
    if (w < 5.0f) {
        w -= 2.5f;
        p = 2.81022636e-08f;
        p = fmaf(p, w,  3.43273939e-07f);
        p = fmaf(p, w, -3.5233877e-06f);
        p = fmaf(p, w, -4.39150654e-06f);
        p = fmaf(p, w,  0.00021858087f);
        p = fmaf(p, w, -0.00125372503f);
        p = fmaf(p, w, -0.00417768164f);
        p = fmaf(p, w,  0.246640727f);
        p = fmaf(p, w,  1.50140941f);
    } else {
        w = sqrtf(w) - 3.0f;
        p = -0.000200214257f;
        p = fmaf(p, w,  0.000100950558f);
        p = fmaf(p, w,  0.00134934322f);
        p = fmaf(p, w, -0.00367342844f);
        p = fmaf(p, w,  0.00573950773f);
        p = fmaf(p, w, -0.0076224613f);
        p = fmaf(p, w,  0.00943887047f);
        p = fmaf(p, w,  1.00167406f);
        p = fmaf(p, w,  2.83297682f);
    }
    return __fmul_rn(1.41421354f, __fmul_rn(p, u));   // sqrt(2)*erfinv(u)
}

// order-isomorphic float map + invidx packing (25-bit value, 7-bit 127-idx)
__device__ __forceinline__ uint32_t pack_key(float v, uint32_t invidx)
{
    uint32_t b = __float_as_uint(v);
    uint32_t k = b ^ ((uint32_t)((int32_t)b >> 31) | 0x80000000u);
    return (k & 0xFFFFFF80u) | invidx;
}

__device__ __forceinline__ uint32_t perturb_pack(float x, uint32_t bits, float sigma,
                                                 uint32_t invidx)
{
    float v = __fadd_rn(x, __fmul_rn(sigma, jx_normal(bits)));
    return pack_key(v, invidx);
}

// decode truncated packed key -> float that is <= the original value (safe low)
__device__ __forceinline__ float decode_key_low(uint32_t k)
{
    uint32_t kv = k & 0xFFFFFF80u;
    uint32_t b  = (kv & 0x80000000u) ? (kv & 0x7FFFFFFFu) : ~kv;
    return __uint_as_float(b);
}

// ---------------------------------------------------------------------------
// Full-128 single-row top-8 (fallback / prep threshold helper pieces)
// ---------------------------------------------------------------------------
#define SWAPD(a,b) { uint32_t t_ = (a) < (b) ? (b) : (a); (b) = (a) < (b) ? (a) : (b); (a) = t_; }

// returns the 8th-largest packed key of 128 keys (4/lane)
__device__ __forceinline__ uint32_t eighth_key(uint32_t a0, uint32_t a1,
                                               uint32_t a2, uint32_t a3)
{
    SWAPD(a0,a1) SWAPD(a2,a3) SWAPD(a0,a2) SWAPD(a1,a3) SWAPD(a1,a2)
    uint32_t mx = 0;
    int pos = 0;
#pragma unroll
    for (int r = 0; r < 8; ++r) {
        mx = __reduce_max_sync(0xffffffffu, a0);
        if (a0 == mx) {
            ++pos;
            a0 = (pos == 1) ? a1 : (pos == 2) ? a2 : (pos == 3) ? a3 : 0u;
        }
    }
    return mx;
}

// full-128 tournament with counting (fallback path only)
__device__ __forceinline__ void topk8_single_accum(
    uint32_t a0, uint32_t a1, uint32_t a2, uint32_t a3,
    int lane, int* __restrict__ scnt)
{
    SWAPD(a0,a1) SWAPD(a2,a3) SWAPD(a0,a2) SWAPD(a1,a3) SWAPD(a1,a2)
    uint32_t wonq = 0;
#pragma unroll
    for (int r = 0; r < 8; ++r) {
        uint32_t mx = __reduce_max_sync(0xffffffffu, a0);
        if (a0 == mx) {
            wonq |= 1u << (3u - ((a0 & 127u) >> 5));
            a0 = a1; a1 = a2; a2 = a3; a3 = 0u;
        }
    }
    uint32_t W0 = __ballot_sync(0xffffffffu,  wonq & 1u);
    uint32_t W1 = __ballot_sync(0xffffffffu, (wonq >> 1) & 1u);
    uint32_t W2 = __ballot_sync(0xffffffffu, (wonq >> 2) & 1u);
    uint32_t W3 = __ballot_sync(0xffffffffu, (wonq >> 3) & 1u);

    int r = lane & 7;
    int c0 = __popc(W0);
    int c01 = c0 + __popc(W1);
    int c012 = c01 + __popc(W2);
    uint32_t word = W0; int base = 0, n = r;
    if (r >= c0)   { word = W1; base = 32; n = r - c0; }
    if (r >= c01)  { word = W2; base = 64; n = r - c01; }
    if (r >= c012) { word = W3; base = 96; n = r - c012; }

    unsigned pos = 0, c;
    c = __popc(word & 0xFFFFu); if ((unsigned)n >= c) { n -= c; pos += 16; word >>= 16; }
    c = __popc(word & 0xFFu);   if ((unsigned)n >= c) { n -= c; pos += 8;  word >>= 8; }
    c = __popc(word & 0xFu);    if ((unsigned)n >= c) { n -= c; pos += 4;  word >>= 4; }
    c = __popc(word & 0x3u);    if ((unsigned)n >= c) { n -= c; pos += 2;  word >>= 2; }
    c = word & 1u;              if ((unsigned)n >= c) { pos += 1; }

    if (lane < 8)
        atomicAdd(&scnt[r * BB + base + (int)pos], 1);
}

// ---------------------------------------------------------------------------
// Kernel 1: pred_sim GEMM + tgt gather + zero counters + candidate lists
// grid(128) block(128). Warps 0/1 build candidates for pred/tgt.
// ---------------------------------------------------------------------------
__global__ void __launch_bounds__(128) prep_kernel(
    const float* __restrict__ cad, const float* __restrict__ scan,
    const float* __restrict__ sim, const int* __restrict__ scannet_idx,
    const int* __restrict__ shapenet_idx,
    float margin1, float margin2)           // 13*sigma per pass
{
    __shared__ float row[DD];
    __shared__ float s_pred[BB], s_tgt[BB];
    int i = blockIdx.x, j = threadIdx.x;
    row[j]       = scan[i * DD + j];
    row[j + 128] = scan[i * DD + 128 + j];

    // zero counters (covers BB*KK*BB per array across the grid)
    {
        int t = (i * 128 + j) * 2;
        int4 z = make_int4(0, 0, 0, 0);
        reinterpret_cast<int4*>(g_cnt1)[t]     = z;
        reinterpret_cast<int4*>(g_cnt1)[t + 1] = z;
        reinterpret_cast<int4*>(g_cnt2)[t]     = z;
        reinterpret_cast<int4*>(g_cnt2)[t + 1] = z;
    }
    __syncthreads();

    const float4* c4 = reinterpret_cast<const float4*>(cad + (size_t)j * DD);
    float acc = 0.0f;
#pragma unroll 8
    for (int t = 0; t < DD / 4; ++t) {
        float4 v = c4[t];
        acc = fmaf(row[4 * t + 0], v.x, acc);
        acc = fmaf(row[4 * t + 1], v.y, acc);
        acc = fmaf(row[4 * t + 2], v.z, acc);
        acc = fmaf(row[4 * t + 3], v.w, acc);
    }
    float tv = sim[(size_t)scannet_idx[i] * NSHAPES + shapenet_idx[j]];
    g_pred[i * BB + j] = acc;  s_pred[j] = acc;
    g_tgt [i * BB + j] = tv;   s_tgt[j]  = tv;
    __syncthreads();

    int w = j >> 5, lane = j & 31;
    if (w < 2) {
        const float* v = w ? s_tgt : s_pred;
        float margin = w ? margin2 : margin1;
        float v0 = v[lane], v1 = v[lane + 32], v2 = v[lane + 64], v3 = v[lane + 96];

        uint32_t k8 = eighth_key(pack_key(v0, 127u - lane),
                                 pack_key(v1, 95u  - lane),
                                 pack_key(v2, 63u  - lane),
                                 pack_key(v3, 31u  - lane));
        float thresh = decode_key_low(k8) - margin;

        int cbase = (w * BB + i) * MAXC;
        int cnt = 0;
#pragma unroll
        for (int q = 0; q < 4; ++q) {
            float vq = (q == 0) ? v0 : (q == 1) ? v1 : (q == 2) ? v2 : v3;
            bool c = (vq >= thresh);
            uint32_t mask = __ballot_sync(0xffffffffu, c);
            if (c) {
                int pos = cnt + __popc(mask & ((1u << lane) - 1u));
                if (pos < MAXC) {
                    g_cval[cbase + pos] = vq;
                    g_cidx[cbase + pos] = q * 32 + lane;
                }
            }
            cnt += __popc(mask);
        }
        if (lane == 0) {
            g_cm[w * BB + i]   = cnt;
            g_over[w * BB + i] = (cnt > MAXC);
        }
    }
}

// ---------------------------------------------------------------------------
// Kernel 2: candidate-pruned noise + top-8 counting, BOTH passes.
// grid(128, C, 2) block(256). Each warp handles 2 samples/iter via
// half-warp segments; lane = candidate slot (<= MAXC=16 per half).
// ---------------------------------------------------------------------------
__global__ void __launch_bounds__(256, 6) cand_topk_kernel(
    uint32_t k0a, uint32_t k1a, uint32_t k0b, uint32_t k1b,
    float sig1, float sig2, int nPerChunk)
{
    int pass = blockIdx.z;
    int rowb = blockIdx.x;
    if (g_over[pass * BB + rowb]) return;        // fallback handles this row

    __shared__ int sCnt[KK * BB];

    int*     __restrict__ cnt = pass ? g_cnt2 : g_cnt1;
    uint32_t k0 = pass ? k0b : k0a;
    uint32_t k1 = pass ? k1b : k1a;
    float sigma = pass ? sig2 : sig1;

    int tid = threadIdx.x;
    for (int t = tid; t < KK * BB; t += 256) sCnt[t] = 0;

    int lane = tid & 31, warp = tid >> 5;
    int slot = lane & 15;
    int m = g_cm[pass * BB + rowb];
    bool active = slot < m;
    int cbase = (pass * BB + rowb) * MAXC;
    float    x   = active ? g_cval[cbase + slot] : 0.0f;
    int      d   = active ? g_cidx[cbase + slot] : 0;
    uint32_t inv = 127u - (uint32_t)d;
    __syncthreads();

    uint32_t halfmask = (lane < 16) ? 0x0000FFFFu : 0xFFFF0000u;
    uint32_t rowbase  = (uint32_t)rowb * (uint32_t)(NSAMP * BB);
    bool     lohalf   = rowb < 64;
    int hsel = lane >> 4;

    int nBegin = blockIdx.y * nPerChunk;
    int nEnd   = nBegin + nPerChunk;

    for (int n = nBegin + 2 * warp; n < nEnd; n += 16) {
        int nn = n + hsel;
        uint32_t e   = rowbase + (uint32_t)nn * (uint32_t)BB + (uint32_t)d;
        uint32_t tx0 = lohalf ? e : e - HALF_ELEMS;
        uint32_t tx1 = lohalf ? e + HALF_ELEMS : e;
        uint32_t o0, o1;
        threefry2x32(k0, k1, tx0, tx1, o0, o1);
        uint32_t rb  = lohalf ? o0 : o1;
        uint32_t key = active ? perturb_pack(x, rb, sigma, inv) : 0u;

        bool won = false;
#pragma unroll
        for (int r = 0; r < 8; ++r) {
            uint32_t mx = __reduce_max_sync(halfmask, key);
            bool wr = (key == mx) && (key != 0u);
            won |= wr;
            key = wr ? 0u : key;
        }
        uint32_t bal = __ballot_sync(0xffffffffu, won);
        if (won) {
            uint32_t hm = (bal >> (hsel << 4)) & 0xFFFFu;
            int rank = __popc(hm & ((1u << slot) - 1u));
            atomicAdd(&sCnt[rank * BB + d], 1);
        }
    }
    __syncthreads();

    for (int t = tid; t < KK * BB; t += 256) {
        int v = sCnt[t];
        if (v) atomicAdd(&cnt[rowb * (KK * BB) + t], v);
    }
}

// ---------------------------------------------------------------------------
// Kernel 2b: full-128 fallback for overflow rows (normally all blocks no-op)
// grid(128, 1, 2) block(256)
// ---------------------------------------------------------------------------
__global__ void __launch_bounds__(256) fallback_kernel(
    uint32_t k0a, uint32_t k1a, uint32_t k0b, uint32_t k1b,
    float sig1, float sig2)
{
    int pass = blockIdx.z;
    int rowb = blockIdx.x;
    if (!g_over[pass * BB + rowb]) return;

    __shared__ float sVal[BB];
    __shared__ int   sCnt[KK * BB];

    const float* __restrict__ src = pass ? g_tgt  : g_pred;
    int*         __restrict__ cnt = pass ? g_cnt2 : g_cnt1;
    uint32_t k0 = pass ? k0b : k0a;
    uint32_t k1 = pass ? k1b : k1a;
    float sigma = pass ? sig2 : sig1;

    int tid = threadIdx.x;
    if (tid < BB) sVal[tid] = src[rowb * BB + tid];
    for (int t = tid; t < KK * BB; t += 256) sCnt[t] = 0;
    __syncthreads();

    int lane = tid & 31, warp = tid >> 5;
    float x0 = sVal[lane], x1 = sVal[lane + 32], x2 = sVal[lane + 64], x3 = sVal[lane + 96];
    uint32_t rowbase = (uint32_t)rowb * (uint32_t)(NSAMP * BB);
    bool lohalf = rowb < 64;

    for (int n = warp; n < NSAMP; n += 8) {
        uint32_t a[4];
#pragma unroll
        for (int q = 0; q < 4; ++q) {
            uint32_t e   = rowbase + (uint32_t)n * (uint32_t)BB + (uint32_t)(lane + 32 * q);
            uint32_t tx0 = lohalf ? e : e - HALF_ELEMS;
            uint32_t tx1 = lohalf ? e + HALF_ELEMS : e;
            uint32_t o0, o1;
            threefry2x32(k0, k1, tx0, tx1, o0, o1);
            uint32_t rb = lohalf ? o0 : o1;
            float xv = (q == 0) ? x0 : (q == 1) ? x1 : (q == 2) ? x2 : x3;
            a[q] = perturb_pack(xv, rb, sigma, (uint32_t)(127 - (lane + 32 * q)));
        }
        topk8_single_accum(a[0], a[1], a[2], a[3], lane, sCnt);
    }
    __syncthreads();

    for (int t = tid; t < KK * BB; t += 256) {
        int v = sCnt[t];
        if (v) atomicAdd(&cnt[rowb * (KK * BB) + t], v);
    }
}

// ---------------------------------------------------------------------------
// Kernel 3/4: deterministic reduction
// loss = -sum(c1*c2*tgt) / (1000*1000*1024). c1*c2 exact in int32.
// ---------------------------------------------------------------------------
__global__ void __launch_bounds__(64) reduce1_kernel()
{
    // 128 blocks x 2 warps; warp handles half a row (512 entries)
    int b    = blockIdx.x;
    int warp = threadIdx.x >> 5;
    int lane = threadIdx.x & 31;
    const int base = b * (KK * BB) + warp * 512;
    float acc = 0.0f;
#pragma unroll
    for (int t = 0; t < 16; ++t) {
        int i = warp * 512 + t * 32 + lane;
        int prod = g_cnt1[b * (KK * BB) + i] * g_cnt2[b * (KK * BB) + i];
        acc = fmaf((float)prod, g_tgt[b * BB + (i & 127)], acc);
    }
    (void)base;
#pragma unroll
    for (int off = 16; off > 0; off >>= 1)
        acc += __shfl_xor_sync(0xffffffffu, acc, off);

    __shared__ float sw[2];
    if (lane == 0) sw[warp] = acc;
    __syncthreads();
    if (threadIdx.x == 0) g_partialf[b] = sw[0] + sw[1];
}

__global__ void __launch_bounds__(128) reduce2_kernel(float* __restrict__ out)
{
    __shared__ float sd[128];
    sd[threadIdx.x] = g_partialf[threadIdx.x];
    __syncthreads();
    for (int s = 64; s > 0; s >>= 1) {
        if (threadIdx.x < s) sd[threadIdx.x] += sd[threadIdx.x + s];
        __syncthreads();
    }
    if (threadIdx.x == 0)
        out[0] = -sd[0] / (1000.0f * 1000.0f * (float)(KK * BB));
}

// ---------------------------------------------------------------------------
// Launch
// ---------------------------------------------------------------------------
extern "C" void kernel_launch(void* const* d_in, const int* in_sizes, int n_in,
                              void* d_out, int out_size)
{
    (void)in_sizes; (void)n_in; (void)out_size;
    const float* cad   = (const float*)d_in[0];
    const float* scan  = (const float*)d_in[1];
    const float* sim   = (const float*)d_in[2];
    const int*   sidx  = (const int*)d_in[3];
    const int*   shidx = (const int*)d_in[4];
    float*       out   = (float*)d_out;

    // nk1, nk2 = jax.random.split(jax.random.key(42)); key(42) = (0, 42)
    uint32_t o00, o10, o01, o11;
    threefry2x32(0u, 42u, 0u, 2u, o00, o10);
    threefry2x32(0u, 42u, 1u, 3u, o01, o11);
    uint32_t nk1_0 = o00, nk1_1 = o01;
    uint32_t nk2_0 = o10, nk2_1 = o11;

    const float sig1 = 0.05f;
    const float sig2 = (float)(0.05 / 200.0);
    const float margin1 = 13.0f * sig1;      // > 2*nmax*sigma, nmax<=6
    const float margin2 = 13.0f * sig2;

    prep_kernel<<<BB, 128>>>(cad, scan, sim, sidx, shidx, margin1, margin2);

    const int NCHUNK = 5;                    // 200 samples per chunk
    dim3 grid(BB, NCHUNK, 2);
    cand_topk_kernel<<<grid, 256>>>(nk1_0, nk1_1, nk2_0, nk2_1,
                                    sig1, sig2, NSAMP / NCHUNK);
    dim3 fgrid(BB, 1, 2);
    fallback_kernel<<<fgrid, 256>>>(nk1_0, nk1_1, nk2_0, nk2_1, sig1, sig2);

    reduce1_kernel<<<BB, 64>>>();
    reduce2_kernel<<<1, 128>>>(out);
}

// round 6
// speedup vs baseline: 10.1684x; 1.6875x over previous
#include <cuda_runtime.h>
#include <cstdint>

// ---------------------------------------------------------------------------
// Problem constants
// ---------------------------------------------------------------------------
#define BB     128          // batch
#define DD     256          // embedding dim
#define NSAMP  1000         // MC samples
#define KK     8            // top-k
#define NSHAPES 8000
#define HALF_ELEMS 8192000u // (128*1000*128)/2 -> element pairing offset
#define MAXC   32           // candidate cap per row (overflow -> inline fallback)

// ---------------------------------------------------------------------------
// Device scratch (no allocations allowed)
// ---------------------------------------------------------------------------
__device__ float  g_pred[BB * BB];
__device__ float  g_tgt [BB * BB];
__device__ int    g_cnt1[BB * KK * BB];   // pred-side indicator counts
__device__ int    g_cnt2[BB * KK * BB];   // tgt-side indicator counts
__device__ float  g_cval[2 * BB * MAXC];  // candidate base values
__device__ int    g_cidx[2 * BB * MAXC];  // candidate global indices (ascending)
__device__ int    g_cm  [2 * BB];         // candidate counts
__device__ unsigned long long g_sum;      // fixed-point loss accumulator
__device__ unsigned int      g_done;      // block completion ticket

// ---------------------------------------------------------------------------
// threefry2x32 — exactly JAX's schedule
// ---------------------------------------------------------------------------
__host__ __device__ __forceinline__ void threefry2x32(
    uint32_t k0, uint32_t k1, uint32_t x0, uint32_t x1,
    uint32_t& o0, uint32_t& o1)
{
    uint32_t ks2 = k0 ^ k1 ^ 0x1BD11BDAu;
#define TF_ROUND(r) { x0 += x1; x1 = (x1 << (r)) | (x1 >> (32 - (r))); x1 ^= x0; }
    x0 += k0; x1 += k1;
    TF_ROUND(13) TF_ROUND(15) TF_ROUND(26) TF_ROUND(6)
    x0 += k1;  x1 += ks2 + 1u;
    TF_ROUND(17) TF_ROUND(29) TF_ROUND(16) TF_ROUND(24)
    x0 += ks2; x1 += k0 + 2u;
    TF_ROUND(13) TF_ROUND(15) TF_ROUND(26) TF_ROUND(6)
    x0 += k0;  x1 += k1 + 3u;
    TF_ROUND(17) TF_ROUND(29) TF_ROUND(16) TF_ROUND(24)
    x0 += k1;  x1 += ks2 + 4u;
    TF_ROUND(13) TF_ROUND(15) TF_ROUND(26) TF_ROUND(6)
    x0 += ks2; x1 += k0 + 5u;
#undef TF_ROUND
    o0 = x0; o1 = x1;
}

// ---------------------------------------------------------------------------
// bits -> N(0,1): JAX uniform bit-trick + XLA ErfInv32 polynomial (fast log).
// |result| <= ~5.43 always (bounded support of the bit-trick uniform).
// ---------------------------------------------------------------------------
__device__ __forceinline__ float jx_normal(uint32_t bits)
{
    float f = __uint_as_float((bits >> 9) | 0x3f800000u) - 1.0f;   // [0,1)
    const float lo = -0.99999994f;                                  // nextafter(-1,0)
    float u = __fadd_rn(__fmul_rn(f, 2.0f), lo);
    u = fmaxf(u, lo);

    float w = -__logf(fmaf(-u, u, 1.0f));     // ~= -log1p(-u*u)
    float p;
    if (w < 5.0f) {
        w -= 2.5f;
        p = 2.81022636e-08f;
        p = fmaf(p, w,  3.43273939e-07f);
        p = fmaf(p, w, -3.5233877e-06f);
        p = fmaf(p, w, -4.39150654e-06f);
        p = fmaf(p, w,  0.00021858087f);
        p = fmaf(p, w, -0.00125372503f);
        p = fmaf(p, w, -0.00417768164f);
        p = fmaf(p, w,  0.246640727f);
        p = fmaf(p, w,  1.50140941f);
    } else {
        w = sqrtf(w) - 3.0f;
        p = -0.000200214257f;
        p = fmaf(p, w,  0.000100950558f);
        p = fmaf(p, w,  0.00134934322f);
        p = fmaf(p, w, -0.00367342844f);
        p = fmaf(p, w,  0.00573950773f);
        p = fmaf(p, w, -0.0076224613f);
        p = fmaf(p, w,  0.00943887047f);
        p = fmaf(p, w,  1.00167406f);
        p = fmaf(p, w,  2.83297682f);
    }
    return __fmul_rn(1.41421354f, __fmul_rn(p, u));   // sqrt(2)*erfinv(u)
}

// order-isomorphic float map + invidx packing (25-bit value, 7-bit 127-idx)
__device__ __forceinline__ uint32_t pack_key(float v, uint32_t invidx)
{
    uint32_t b = __float_as_uint(v);
    uint32_t k = b ^ ((uint32_t)((int32_t)b >> 31) | 0x80000000u);
    return (k & 0xFFFFFF80u) | invidx;
}

__device__ __forceinline__ uint32_t perturb_pack(float x, uint32_t bits, float sigma,
                                                 uint32_t invidx)
{
    float v = __fadd_rn(x, __fmul_rn(sigma, jx_normal(bits)));
    return pack_key(v, invidx);
}

// decode truncated packed key -> float that is <= the original value (safe low)
__device__ __forceinline__ float decode_key_low(uint32_t k)
{
    uint32_t kv = k & 0xFFFFFF80u;
    uint32_t b  = (kv & 0x80000000u) ? (kv & 0x7FFFFFFFu) : ~kv;
    return __uint_as_float(b);
}

// ---------------------------------------------------------------------------
// Full-128 helpers (prep threshold + inline fallback)
// ---------------------------------------------------------------------------
#define SWAPD(a,b) { uint32_t t_ = (a) < (b) ? (b) : (a); (b) = (a) < (b) ? (a) : (b); (a) = t_; }

// returns the 8th-largest packed key of 128 keys (4/lane)
__device__ __forceinline__ uint32_t eighth_key(uint32_t a0, uint32_t a1,
                                               uint32_t a2, uint32_t a3)
{
    SWAPD(a0,a1) SWAPD(a2,a3) SWAPD(a0,a2) SWAPD(a1,a3) SWAPD(a1,a2)
    uint32_t mx = 0;
    int pos = 0;
#pragma unroll
    for (int r = 0; r < 8; ++r) {
        mx = __reduce_max_sync(0xffffffffu, a0);
        if (a0 == mx) {
            ++pos;
            a0 = (pos == 1) ? a1 : (pos == 2) ? a2 : (pos == 3) ? a3 : 0u;
        }
    }
    return mx;
}

// full-128 tournament with counting (inline fallback path only)
__device__ __forceinline__ void topk8_single_accum(
    uint32_t a0, uint32_t a1, uint32_t a2, uint32_t a3,
    int lane, int* __restrict__ scnt)
{
    SWAPD(a0,a1) SWAPD(a2,a3) SWAPD(a0,a2) SWAPD(a1,a3) SWAPD(a1,a2)
    uint32_t wonq = 0;
#pragma unroll
    for (int r = 0; r < 8; ++r) {
        uint32_t mx = __reduce_max_sync(0xffffffffu, a0);
        if (a0 == mx) {
            wonq |= 1u << (3u - ((a0 & 127u) >> 5));
            a0 = a1; a1 = a2; a2 = a3; a3 = 0u;
        }
    }
    uint32_t W0 = __ballot_sync(0xffffffffu,  wonq & 1u);
    uint32_t W1 = __ballot_sync(0xffffffffu, (wonq >> 1) & 1u);
    uint32_t W2 = __ballot_sync(0xffffffffu, (wonq >> 2) & 1u);
    uint32_t W3 = __ballot_sync(0xffffffffu, (wonq >> 3) & 1u);

    int r = lane & 7;
    int c0 = __popc(W0);
    int c01 = c0 + __popc(W1);
    int c012 = c01 + __popc(W2);
    uint32_t word = W0; int base = 0, n = r;
    if (r >= c0)   { word = W1; base = 32; n = r - c0; }
    if (r >= c01)  { word = W2; base = 64; n = r - c01; }
    if (r >= c012) { word = W3; base = 96; n = r - c012; }

    unsigned pos = 0, c;
    c = __popc(word & 0xFFFFu); if ((unsigned)n >= c) { n -= c; pos += 16; word >>= 16; }
    c = __popc(word & 0xFFu);   if ((unsigned)n >= c) { n -= c; pos += 8;  word >>= 8; }
    c = __popc(word & 0xFu);    if ((unsigned)n >= c) { n -= c; pos += 4;  word >>= 4; }
    c = __popc(word & 0x3u);    if ((unsigned)n >= c) { n -= c; pos += 2;  word >>= 2; }
    c = word & 1u;              if ((unsigned)n >= c) { pos += 1; }

    if (lane < 8)
        atomicAdd(&scnt[r * BB + base + (int)pos], 1);
}

// ---------------------------------------------------------------------------
// Kernel 1: pred_sim GEMM + tgt gather + zero counters/accum + candidates
// grid(128) block(128). Warps 0/1 build candidates for pred/tgt.
// ---------------------------------------------------------------------------
__global__ void __launch_bounds__(128) prep_kernel(
    const float* __restrict__ cad, const float* __restrict__ scan,
    const float* __restrict__ sim, const int* __restrict__ scannet_idx,
    const int* __restrict__ shapenet_idx,
    float margin1, float margin2)           // 13*sigma per pass
{
    __shared__ float row[DD];
    __shared__ float s_pred[BB], s_tgt[BB];
    int i = blockIdx.x, j = threadIdx.x;
    row[j]       = scan[i * DD + j];
    row[j + 128] = scan[i * DD + 128 + j];

    // zero counters + accumulators
    {
        int t = (i * 128 + j) * 2;
        int4 z = make_int4(0, 0, 0, 0);
        reinterpret_cast<int4*>(g_cnt1)[t]     = z;
        reinterpret_cast<int4*>(g_cnt1)[t + 1] = z;
        reinterpret_cast<int4*>(g_cnt2)[t]     = z;
        reinterpret_cast<int4*>(g_cnt2)[t + 1] = z;
    }
    if (i == 0 && j == 0) { g_sum = 0ull; g_done = 0u; }
    __syncthreads();

    const float4* c4 = reinterpret_cast<const float4*>(cad + (size_t)j * DD);
    float acc = 0.0f;
#pragma unroll 8
    for (int t = 0; t < DD / 4; ++t) {
        float4 v = c4[t];
        acc = fmaf(row[4 * t + 0], v.x, acc);
        acc = fmaf(row[4 * t + 1], v.y, acc);
        acc = fmaf(row[4 * t + 2], v.z, acc);
        acc = fmaf(row[4 * t + 3], v.w, acc);
    }
    float tv = sim[(size_t)scannet_idx[i] * NSHAPES + shapenet_idx[j]];
    g_pred[i * BB + j] = acc;  s_pred[j] = acc;
    g_tgt [i * BB + j] = tv;   s_tgt[j]  = tv;
    __syncthreads();

    int w = j >> 5, lane = j & 31;
    if (w < 2) {
        const float* v = w ? s_tgt : s_pred;
        float margin = w ? margin2 : margin1;
        float v0 = v[lane], v1 = v[lane + 32], v2 = v[lane + 64], v3 = v[lane + 96];

        uint32_t k8 = eighth_key(pack_key(v0, 127u - lane),
                                 pack_key(v1, 95u  - lane),
                                 pack_key(v2, 63u  - lane),
                                 pack_key(v3, 31u  - lane));
        float thresh = decode_key_low(k8) - margin;

        int cbase = (w * BB + i) * MAXC;
        int cnt = 0;
#pragma unroll
        for (int q = 0; q < 4; ++q) {
            float vq = (q == 0) ? v0 : (q == 1) ? v1 : (q == 2) ? v2 : v3;
            bool c = (vq >= thresh);
            uint32_t mask = __ballot_sync(0xffffffffu, c);
            if (c) {
                int pos = cnt + __popc(mask & ((1u << lane) - 1u));
                if (pos < MAXC) {
                    g_cval[cbase + pos] = vq;
                    g_cidx[cbase + pos] = q * 32 + lane;
                }
            }
            cnt += __popc(mask);
        }
        if (lane == 0) g_cm[w * BB + i] = cnt;
    }
}

// ---------------------------------------------------------------------------
// Kernel 2: candidate-pruned noise + top-8 counting, BOTH passes.
// grid(128, NCHUNK, 2) block(256). Dynamic segmentation: 32/m samples/warp.
// Selection: eliminate bottom (m-8) via REDUX.MIN when m<=16, else 8 MAX
// rounds. m>32 -> inline full-128 fallback.
// ---------------------------------------------------------------------------
__global__ void __launch_bounds__(256, 6) cand_topk_kernel(
    uint32_t k0a, uint32_t k1a, uint32_t k0b, uint32_t k1b,
    float sig1, float sig2, int nPerChunk)
{
    int pass = blockIdx.z;
    int rowb = blockIdx.x;

    __shared__ int sCnt[KK * BB];

    int*     __restrict__ cnt = pass ? g_cnt2 : g_cnt1;
    uint32_t k0 = pass ? k0b : k0a;
    uint32_t k1 = pass ? k1b : k1a;
    float sigma = pass ? sig2 : sig1;

    int tid = threadIdx.x;
    int lane = tid & 31, warp = tid >> 5;
    for (int t = tid; t < KK * BB; t += 256) sCnt[t] = 0;

    int m = g_cm[pass * BB + rowb];
    uint32_t rowbase = (uint32_t)rowb * (uint32_t)(NSAMP * BB);
    bool lohalf = rowb < 64;
    int nBegin = blockIdx.y * nPerChunk;
    int nEnd   = nBegin + nPerChunk;

    if (m <= MAXC) {
        int nseg = 32 / m;
        int seg  = lane / m;
        int slot = lane - seg * m;
        bool active = seg < nseg;
        uint32_t segmask = ((m == 32) ? 0xffffffffu : ((1u << m) - 1u)) << (seg * m);

        int cbase = (pass * BB + rowb) * MAXC;
        float    x   = active ? g_cval[cbase + slot] : 0.0f;
        int      d   = active ? g_cidx[cbase + slot] : 0;
        uint32_t inv = 127u - (uint32_t)d;
        __syncthreads();

        int roundsMin = m - 8;
        bool useMin = (roundsMin <= 8);

        for (int n0 = nBegin + warp * nseg; n0 < nEnd; n0 += 8 * nseg) {
            int nn = n0 + seg;
            bool valid = active && (nn < nEnd);

            uint32_t e   = rowbase + (uint32_t)nn * (uint32_t)BB + (uint32_t)d;
            uint32_t tx0 = lohalf ? e : e - HALF_ELEMS;
            uint32_t tx1 = lohalf ? e + HALF_ELEMS : e;
            uint32_t o0, o1;
            threefry2x32(k0, k1, tx0, tx1, o0, o1);
            uint32_t rb = lohalf ? o0 : o1;

            bool won = false;
            if (valid) {                       // segment-uniform branch
                uint32_t key = perturb_pack(x, rb, sigma, inv);
                if (useMin) {
                    bool elim = false;
                    for (int r = 0; r < roundsMin; ++r) {
                        uint32_t mn = __reduce_min_sync(segmask, key);
                        bool er = (key == mn);
                        elim |= er;
                        if (er) key = 0xFFFFFFFFu;
                    }
                    won = !elim;
                } else {
                    for (int r = 0; r < 8; ++r) {
                        uint32_t mx = __reduce_max_sync(segmask, key);
                        bool wr = (key == mx);
                        won |= wr;
                        if (wr) key = 0u;
                    }
                }
            }
            uint32_t bal = __ballot_sync(0xffffffffu, won);
            if (won) {
                int rank = __popc(bal & segmask & ((1u << lane) - 1u));
                atomicAdd(&sCnt[rank * BB + d], 1);
            }
        }
    } else {
        // inline full-128 fallback (m > 32; astronomically rare)
        __shared__ float sVal[BB];
        const float* __restrict__ src = pass ? g_tgt : g_pred;
        if (tid < BB) sVal[tid] = src[rowb * BB + tid];
        __syncthreads();

        float x0 = sVal[lane], x1 = sVal[lane + 32], x2 = sVal[lane + 64], x3 = sVal[lane + 96];
        for (int n = nBegin + warp; n < nEnd; n += 8) {
            uint32_t a[4];
#pragma unroll
            for (int q = 0; q < 4; ++q) {
                uint32_t e   = rowbase + (uint32_t)n * (uint32_t)BB + (uint32_t)(lane + 32 * q);
                uint32_t tx0 = lohalf ? e : e - HALF_ELEMS;
                uint32_t tx1 = lohalf ? e + HALF_ELEMS : e;
                uint32_t o0, o1;
                threefry2x32(k0, k1, tx0, tx1, o0, o1);
                uint32_t rb = lohalf ? o0 : o1;
                float xv = (q == 0) ? x0 : (q == 1) ? x1 : (q == 2) ? x2 : x3;
                a[q] = perturb_pack(xv, rb, sigma, (uint32_t)(127 - (lane + 32 * q)));
            }
            topk8_single_accum(a[0], a[1], a[2], a[3], lane, sCnt);
        }
    }
    __syncthreads();

    for (int t = tid; t < KK * BB; t += 256) {
        int v = sCnt[t];
        if (v) atomicAdd(&cnt[rowb * (KK * BB) + t], v);
    }
}

// ---------------------------------------------------------------------------
// Kernel 3: fused deterministic reduction.
// Per-row fp32 partial -> 2^20 fixed-point int64 atomic (order-independent)
// -> last block writes the scalar. loss = -sum / (1000*1000*1024).
// ---------------------------------------------------------------------------
__global__ void __launch_bounds__(128) reduce_kernel(float* __restrict__ out)
{
    int b = blockIdx.x;
    int tid = threadIdx.x;
    float acc = 0.0f;
#pragma unroll
    for (int t = 0; t < 8; ++t) {
        int i = t * 128 + tid;
        int prod = g_cnt1[b * (KK * BB) + i] * g_cnt2[b * (KK * BB) + i];
        acc = fmaf((float)prod, g_tgt[b * BB + (i & 127)], acc);
    }
#pragma unroll
    for (int off = 16; off > 0; off >>= 1)
        acc += __shfl_xor_sync(0xffffffffu, acc, off);

    __shared__ float sw[4];
    if ((tid & 31) == 0) sw[tid >> 5] = acc;
    __syncthreads();
    if (tid == 0) {
        float partial = sw[0] + sw[1] + sw[2] + sw[3];
        long long fx = llrintf(partial * 1048576.0f);
        atomicAdd(&g_sum, (unsigned long long)fx);
        __threadfence();
        if (atomicAdd(&g_done, 1u) == (unsigned)(BB - 1)) {
            unsigned long long s = atomicAdd(&g_sum, 0ull);
            double total = (double)(long long)s / 1048576.0;
            out[0] = (float)(-total / (1000.0 * 1000.0 * (double)(KK * BB)));
        }
    }
}

// ---------------------------------------------------------------------------
// Launch
// ---------------------------------------------------------------------------
extern "C" void kernel_launch(void* const* d_in, const int* in_sizes, int n_in,
                              void* d_out, int out_size)
{
    (void)in_sizes; (void)n_in; (void)out_size;
    const float* cad   = (const float*)d_in[0];
    const float* scan  = (const float*)d_in[1];
    const float* sim   = (const float*)d_in[2];
    const int*   sidx  = (const int*)d_in[3];
    const int*   shidx = (const int*)d_in[4];
    float*       out   = (float*)d_out;

    // nk1, nk2 = jax.random.split(jax.random.key(42)); key(42) = (0, 42)
    uint32_t o00, o10, o01, o11;
    threefry2x32(0u, 42u, 0u, 2u, o00, o10);
    threefry2x32(0u, 42u, 1u, 3u, o01, o11);
    uint32_t nk1_0 = o00, nk1_1 = o01;
    uint32_t nk2_0 = o10, nk2_1 = o11;

    const float sig1 = 0.05f;
    const float sig2 = (float)(0.05 / 200.0);
    const float margin1 = 13.0f * sig1;      // > 2*nmax*sigma, nmax<=6
    const float margin2 = 13.0f * sig2;

    prep_kernel<<<BB, 128>>>(cad, scan, sim, sidx, shidx, margin1, margin2);

    const int NCHUNK = 10;                   // 100 samples per chunk
    dim3 grid(BB, NCHUNK, 2);
    cand_topk_kernel<<<grid, 256>>>(nk1_0, nk1_1, nk2_0, nk2_1,
                                    sig1, sig2, NSAMP / NCHUNK);

    reduce_kernel<<<BB, 128>>>(out);
}